// round 3
// baseline (speedup 1.0000x reference)
#include <cuda_runtime.h>
#include <math.h>

#define NB   8
#define SS   4096
#define DD   1024
#define DKK  512
#define NH   8
#define WW   128
#define DH   64
#define NWIN 32   // S / W

// Scratch (device globals: allowed; no cudaMalloc anywhere)
__device__ float g_Q[(size_t)NB * DKK * SS];
__device__ float g_K[(size_t)NB * DKK * SS];
__device__ float g_V[(size_t)NB * DKK * SS];
__device__ float g_O[(size_t)NB * DKK * SS];

// ---------------------------------------------------------------------------
// SGEMM: C[b] = A @ B[b] + bias (row-major, M,N,K all multiples of 128/128/8)
// A: [M,K], B: [K,N] per batch (stride K*N), C: [M,N] per batch (stride M*N)
// USE_MASK: multiply column n of batch b by cmask[b*N + n] (final projection)
// ---------------------------------------------------------------------------
template<bool USE_MASK>
__global__ __launch_bounds__(256, 2) void sgemm_bias(
    const float* __restrict__ A,
    const float* __restrict__ Bmat,
    const float* __restrict__ bias,
    const float* __restrict__ cmask,
    float* __restrict__ C,
    int M, int N, int K)
{
    const int bx = blockIdx.x, by = blockIdx.y, bz = blockIdx.z;
    const float* Bp = Bmat + (size_t)bz * K * N;
    float*       Cp = C    + (size_t)bz * M * N;

    __shared__ float As[8][128];
    __shared__ float Bs[8][128];

    const int tid = threadIdx.x;
    const int tx = tid & 15, ty = tid >> 4;

    // load indices
    const int arow = tid >> 1;          // 0..127
    const int akq  = (tid & 1) * 4;     // 0 or 4
    const int brow = tid >> 5;          // 0..7
    const int bcol = (tid & 31) * 4;    // 0..124

    const float* Aload = A  + (size_t)(by * 128 + arow) * K + akq;
    const float* Bload = Bp + (size_t)brow * N + bx * 128 + bcol;

    float acc[8][8];
    #pragma unroll
    for (int u = 0; u < 8; u++)
        #pragma unroll
        for (int v = 0; v < 8; v++) acc[u][v] = 0.f;

    float4 aST = *(const float4*)(Aload);
    float4 bST = *(const float4*)(Bload);

    #pragma unroll 1
    for (int k0 = 0; k0 < K; k0 += 8) {
        __syncthreads();
        As[akq + 0][arow] = aST.x;
        As[akq + 1][arow] = aST.y;
        As[akq + 2][arow] = aST.z;
        As[akq + 3][arow] = aST.w;
        *(float4*)&Bs[brow][bcol] = bST;
        __syncthreads();

        if (k0 + 8 < K) {   // prefetch next tile (overlaps with compute)
            aST = *(const float4*)(Aload + k0 + 8);
            bST = *(const float4*)(Bload + (size_t)(k0 + 8) * N);
        }

        #pragma unroll
        for (int kk = 0; kk < 8; kk++) {
            float ra[8], rb[8];
            *(float4*)(ra)     = *(const float4*)&As[kk][ty * 8];
            *(float4*)(ra + 4) = *(const float4*)&As[kk][ty * 8 + 4];
            *(float4*)(rb)     = *(const float4*)&Bs[kk][tx * 8];
            *(float4*)(rb + 4) = *(const float4*)&Bs[kk][tx * 8 + 4];
            #pragma unroll
            for (int u = 0; u < 8; u++)
                #pragma unroll
                for (int v = 0; v < 8; v++)
                    acc[u][v] += ra[u] * rb[v];
        }
    }

    const int m0 = by * 128 + ty * 8;
    const int n0 = bx * 128 + tx * 8;
    const float* cm = USE_MASK ? (cmask + (size_t)bz * N) : nullptr;

    #pragma unroll
    for (int u = 0; u < 8; u++) {
        const float bb = bias[m0 + u];
        float* crow = Cp + (size_t)(m0 + u) * N + n0;
        float r[8];
        #pragma unroll
        for (int v = 0; v < 8; v++) {
            float val = acc[u][v] + bb;
            if (USE_MASK) val *= cm[n0 + v];
            r[v] = val;
        }
        *(float4*)(crow)     = *(float4*)(r);
        *(float4*)(crow + 4) = *(float4*)(r + 4);
    }
}

// ---------------------------------------------------------------------------
// Fused windowed attention per (window, head) CTA:
//   scores = (Q^T K)/8, key mask, softmax, O = V @ attn^T, exact GELU.
// Smem: [qs|ks] 64KB (overlaid by attnT 128x128 after scores), vsT, reduce buf.
// ---------------------------------------------------------------------------
#define ATTN_SMEM_FLOATS (128*128 + 128*68 + 128*16 + 128)
#define ATTN_SMEM_BYTES  (ATTN_SMEM_FLOATS * 4)

__device__ __forceinline__ float gelu_exact(float x) { return x * normcdff(x); }

__global__ __launch_bounds__(256, 2) void attn_kernel(const float* __restrict__ masks)
{
    extern __shared__ float sm[];
    float* qs    = sm;                    // [64][128]
    float* ks    = sm + 64 * 128;         // [64][128]
    float* attnT = sm;                    // [128][128] overlays qs+ks (exactly 16384 floats)
    float* vsT   = sm + 128 * 128;        // [128][68]  (transposed V, padded)
    float* red   = vsT + 128 * 68;        // [128][16]
    float* msk   = red + 128 * 16;        // [128]

    const int tid = threadIdx.x;
    const int wh  = blockIdx.x;           // 0..255
    const int w   = wh >> 3;
    const int h   = wh & 7;
    const int b   = blockIdx.y;

    const size_t base = (size_t)b * DKK * SS + (size_t)h * DH * SS + (size_t)w * WW;

    // ---- load Q, K (d-major) and V (transposed) into smem ----
    #pragma unroll
    for (int r = 0; r < 8; r++) {
        int idx = tid + 256 * r;          // 0..2047
        int d   = idx >> 5;               // 0..63
        int i4  = (idx & 31) << 2;        // 0..124
        size_t g = base + (size_t)d * SS + i4;
        float4 qv = *(const float4*)(g_Q + g);
        float4 kv = *(const float4*)(g_K + g);
        float4 vv = *(const float4*)(g_V + g);
        *(float4*)(qs + d * 128 + i4) = qv;
        *(float4*)(ks + d * 128 + i4) = kv;
        vsT[(i4 + 0) * 68 + d] = vv.x;
        vsT[(i4 + 1) * 68 + d] = vv.y;
        vsT[(i4 + 2) * 68 + d] = vv.z;
        vsT[(i4 + 3) * 68 + d] = vv.w;
    }
    if (tid < 32) {
        float4 mv = *(const float4*)(masks + (size_t)b * SS + w * WW + tid * 4);
        *(float4*)(msk + tid * 4) = mv;
    }
    __syncthreads();

    // ---- scores = Q^T K (register 8x8 tiles) ----
    const int tx = tid & 15, ty = tid >> 4;
    const int i0 = ty * 8, j0 = tx * 8;

    float acc[8][8];
    #pragma unroll
    for (int u = 0; u < 8; u++)
        #pragma unroll
        for (int v = 0; v < 8; v++) acc[u][v] = 0.f;

    #pragma unroll 8
    for (int d = 0; d < DH; d++) {
        float ra[8], rb[8];
        *(float4*)(ra)     = *(const float4*)(qs + d * 128 + i0);
        *(float4*)(ra + 4) = *(const float4*)(qs + d * 128 + i0 + 4);
        *(float4*)(rb)     = *(const float4*)(ks + d * 128 + j0);
        *(float4*)(rb + 4) = *(const float4*)(ks + d * 128 + j0 + 4);
        #pragma unroll
        for (int u = 0; u < 8; u++)
            #pragma unroll
            for (int v = 0; v < 8; v++)
                acc[u][v] += ra[u] * rb[v];
    }

    // scale + key mask
    float mj[8];
    #pragma unroll
    for (int v = 0; v < 8; v++) mj[v] = msk[j0 + v];
    #pragma unroll
    for (int u = 0; u < 8; u++)
        #pragma unroll
        for (int v = 0; v < 8; v++)
            acc[u][v] = (mj[v] > 0.f) ? acc[u][v] * 0.125f : -1e9f;

    // ---- softmax over j (rows split across 16 tx threads) ----
    #pragma unroll
    for (int u = 0; u < 8; u++) {
        float pm = acc[u][0];
        #pragma unroll
        for (int v = 1; v < 8; v++) pm = fmaxf(pm, acc[u][v]);
        red[(i0 + u) * 16 + tx] = pm;
    }
    __syncthreads();   // also: last qs/ks read is above -> attnT overlay now safe

    float rmax[8];
    #pragma unroll
    for (int u = 0; u < 8; u++) {
        float m = red[(i0 + u) * 16];
        #pragma unroll
        for (int t = 1; t < 16; t++) m = fmaxf(m, red[(i0 + u) * 16 + t]);
        rmax[u] = m;
    }
    __syncthreads();

    #pragma unroll
    for (int u = 0; u < 8; u++) {
        float s = 0.f;
        #pragma unroll
        for (int v = 0; v < 8; v++) {
            float e = expf(acc[u][v] - rmax[u]);
            acc[u][v] = e;
            s += e;
        }
        red[(i0 + u) * 16 + tx] = s;
    }
    __syncthreads();

    float inv[8];
    #pragma unroll
    for (int u = 0; u < 8; u++) {
        float s = 0.f;
        #pragma unroll
        for (int t = 0; t < 16; t++) s += red[(i0 + u) * 16 + t];
        inv[u] = 1.f / s;
    }

    // write normalized attention transposed: attnT[j][i]
    #pragma unroll
    for (int v = 0; v < 8; v++) {
        float4 w0 = make_float4(acc[0][v] * inv[0], acc[1][v] * inv[1],
                                acc[2][v] * inv[2], acc[3][v] * inv[3]);
        float4 w1 = make_float4(acc[4][v] * inv[4], acc[5][v] * inv[5],
                                acc[6][v] * inv[6], acc[7][v] * inv[7]);
        *(float4*)(attnT + (j0 + v) * 128 + i0)     = w0;
        *(float4*)(attnT + (j0 + v) * 128 + i0 + 4) = w1;
    }
    __syncthreads();

    // ---- O[d][i] = sum_j vsT[j][d] * attnT[j][i]  (4x8 register tiles) ----
    const int txa = tid & 15, tya = tid >> 4;
    const int ia  = txa * 8;
    const int d0  = tya * 4;

    float oacc[4][8];
    #pragma unroll
    for (int t = 0; t < 4; t++)
        #pragma unroll
        for (int u = 0; u < 8; u++) oacc[t][u] = 0.f;

    #pragma unroll 4
    for (int j = 0; j < 128; j++) {
        float a8[8], v4[4];
        *(float4*)(a8)     = *(const float4*)(attnT + j * 128 + ia);
        *(float4*)(a8 + 4) = *(const float4*)(attnT + j * 128 + ia + 4);
        *(float4*)(v4)     = *(const float4*)(vsT + j * 68 + d0);
        #pragma unroll
        for (int t = 0; t < 4; t++)
            #pragma unroll
            for (int u = 0; u < 8; u++)
                oacc[t][u] += v4[t] * a8[u];
    }

    // exact GELU + store
    #pragma unroll
    for (int t = 0; t < 4; t++) {
        size_t g = base + (size_t)(d0 + t) * SS + ia;
        float r[8];
        #pragma unroll
        for (int u = 0; u < 8; u++) r[u] = gelu_exact(oacc[t][u]);
        *(float4*)(g_O + g)     = *(float4*)(r);
        *(float4*)(g_O + g + 4) = *(float4*)(r + 4);
    }
}

// ---------------------------------------------------------------------------
extern "C" void kernel_launch(void* const* d_in, const int* in_sizes, int n_in,
                              void* d_out, int out_size)
{
    const float* qk    = (const float*)d_in[0];
    const float* v     = (const float*)d_in[1];
    const float* masks = (const float*)d_in[2];
    const float* Wq    = (const float*)d_in[3];
    const float* bq    = (const float*)d_in[4];
    const float* Wk    = (const float*)d_in[5];
    const float* bk    = (const float*)d_in[6];
    const float* Wv    = (const float*)d_in[7];
    const float* bv    = (const float*)d_in[8];
    const float* Wo    = (const float*)d_in[9];
    const float* bo    = (const float*)d_in[10];
    float* out = (float*)d_out;

    float *Q, *K, *V, *O;
    cudaGetSymbolAddress((void**)&Q, g_Q);
    cudaGetSymbolAddress((void**)&K, g_K);
    cudaGetSymbolAddress((void**)&V, g_V);
    cudaGetSymbolAddress((void**)&O, g_O);

    cudaFuncSetAttribute(attn_kernel,
                         cudaFuncAttributeMaxDynamicSharedMemorySize,
                         ATTN_SMEM_BYTES);

    dim3 blk(256);
    // Q/K/V projections: [512,1024] x [1024,4096] per batch
    sgemm_bias<false><<<dim3(32, 4, NB), blk>>>(Wq, qk, bq, nullptr, Q, DKK, SS, DD);
    sgemm_bias<false><<<dim3(32, 4, NB), blk>>>(Wk, qk, bk, nullptr, K, DKK, SS, DD);
    sgemm_bias<false><<<dim3(32, 4, NB), blk>>>(Wv, v,  bv, nullptr, V, DKK, SS, DD);

    // attention + GELU: one CTA per (window, head)
    attn_kernel<<<dim3(NWIN * NH, NB), blk, ATTN_SMEM_BYTES>>>(masks);

    // output projection + final mask: [1024,512] x [512,4096] per batch
    sgemm_bias<true><<<dim3(32, 8, NB), blk>>>(Wo, O, bo, masks, out, DD, SS, DKK);
}

// round 5
// speedup vs baseline: 1.6638x; 1.6638x over previous
#include <cuda_runtime.h>
#include <cuda_bf16.h>
#include <math.h>
#include <stdint.h>

#define NB   8
#define SS   4096
#define DD   1024
#define DKK  512
#define NH   8
#define WW   128
#define DH   64
#define NWIN 32   // S / W

// Scratch (device globals: allowed; no cudaMalloc anywhere)
__device__ float g_Q[(size_t)NB * DKK * SS];
__device__ float g_K[(size_t)NB * DKK * SS];
__device__ float g_V[(size_t)NB * DKK * SS];
__device__ float g_O[(size_t)NB * DKK * SS];

// ============================================================================
// Warp-MMA helpers (sm_80+ PTX — valid for compute_103, no 'a' features)
// ============================================================================
__device__ __forceinline__ uint32_t smem_u32(const void* p) {
    uint32_t a;
    asm("{ .reg .u64 t; cvta.to.shared.u64 t, %1; cvt.u32.u64 %0, t; }"
        : "=r"(a) : "l"(p));
    return a;
}
__device__ __forceinline__ void ldsm_x4(uint32_t* r, uint32_t addr) {
    asm volatile("ldmatrix.sync.aligned.m8n8.x4.shared.b16 {%0,%1,%2,%3}, [%4];"
                 : "=r"(r[0]), "=r"(r[1]), "=r"(r[2]), "=r"(r[3]) : "r"(addr));
}
__device__ __forceinline__ void ldsm_x2_trans(uint32_t* r, uint32_t addr) {
    asm volatile("ldmatrix.sync.aligned.m8n8.x2.trans.shared.b16 {%0,%1}, [%2];"
                 : "=r"(r[0]), "=r"(r[1]) : "r"(addr));
}
__device__ __forceinline__ void mma16816(float* d, const uint32_t* a, const uint32_t* b) {
    asm volatile(
        "mma.sync.aligned.m16n8k16.row.col.f32.bf16.bf16.f32 "
        "{%0,%1,%2,%3},{%4,%5,%6,%7},{%8,%9},{%0,%1,%2,%3};"
        : "+f"(d[0]), "+f"(d[1]), "+f"(d[2]), "+f"(d[3])
        : "r"(a[0]), "r"(a[1]), "r"(a[2]), "r"(a[3]), "r"(b[0]), "r"(b[1]));
}
__device__ __forceinline__ void split_bf16(float x, unsigned& h, unsigned& l) {
    __nv_bfloat16 bh = __float2bfloat16_rn(x);
    float r = __fsub_rn(x, __bfloat162float(bh));
    __nv_bfloat16 bl = __float2bfloat16_rn(r);
    h = (unsigned)__bfloat16_as_ushort(bh);
    l = (unsigned)__bfloat16_as_ushort(bl);
}

// ============================================================================
// bf16x3 SGEMM via mma.sync:  C[bz] = A @ X[bz] + bias (fp32 in/out)
// A: [M,K] row-major (shared across batch), X: [K,N] per batch, C: [M,N].
// CTA tile 128x128, 8 warps (2x4), warp tile 64x32, K-chunk 32, double buffer.
// A smem: [m(128)][k(32)] bf16 pitch 40 elems (80B)  -> conflict-free ldmatrix
// B smem: [k(32)][n(128)] bf16 pitch 136 elems(272B) -> conflict-free x2.trans
// ============================================================================
#define APITCH  40      // bf16 elems per A row (80 B)
#define BPITCH  136     // bf16 elems per B row (272 B)
#define OFF_AH  0
#define OFF_AL  (128 * APITCH * 2)                 // 10240
#define OFF_BH  (OFF_AL + 128 * APITCH * 2)        // 20480
#define OFF_BL  (OFF_BH + 32 * BPITCH * 2)         // 29184
#define BUF_SZ  (OFF_BL + 32 * BPITCH * 2)         // 37888
#define GSMEM_TOTAL (2 * BUF_SZ)                   // 75776

template<bool USE_MASK>
__global__ __launch_bounds__(256, 1) void gemm_mma(
    const float* __restrict__ A,
    const float* __restrict__ X,
    const float* __restrict__ bias,
    const float* __restrict__ cmask,
    float* __restrict__ C,
    int M, int N, int K)
{
    extern __shared__ char sm[];
    const int tid  = threadIdx.x;
    const int warp = tid >> 5;
    const int lane = tid & 31;
    const int bx = blockIdx.x, by = blockIdx.y, bz = blockIdx.z;
    const int n0 = bx * 128, m0 = by * 128;
    const int wm = (warp >> 2) * 64;     // warp m offset (0 or 64)
    const int wn = (warp & 3) * 32;      // warp n offset

    const float* Xb = X + (size_t)bz * K * N;
    float*       Cb = C + (size_t)bz * M * N;
    const uint32_t smb = smem_u32(sm);

    const int arow = tid >> 3, ag = tid & 7;     // A load: 128 rows x 8 groups
    const int bk   = tid >> 5, bg = tid & 31;    // X load: 32 k x 32 groups

    float4 pa[4], px[4];

    // ---- global load of one chunk into registers ----
    auto load_chunk = [&](int c) {
        const float* Ach = A  + (size_t)m0 * K + c * 32;
        const float* Xch = Xb + (size_t)(c * 32) * N + n0;
        #pragma unroll
        for (int it = 0; it < 4; it++) {
            pa[it] = *(const float4*)(Ach + (size_t)(arow + it * 32) * K + ag * 4);
            px[it] = *(const float4*)(Xch + (size_t)(bk + it * 8) * N + bg * 4);
        }
    };
    // ---- split regs -> smem buffer ----
    auto store_chunk = [&](int buf) {
        char* bp = sm + buf * BUF_SZ;
        #pragma unroll
        for (int it = 0; it < 4; it++) {
            unsigned h0,l0,h1,l1,h2,l2,h3,l3;
            split_bf16(pa[it].x, h0, l0); split_bf16(pa[it].y, h1, l1);
            split_bf16(pa[it].z, h2, l2); split_bf16(pa[it].w, h3, l3);
            unsigned off = (unsigned)((arow + it * 32) * APITCH * 2 + ag * 8);
            *(uint2*)(bp + OFF_AH + off) = make_uint2(h0 | (h1 << 16), h2 | (h3 << 16));
            *(uint2*)(bp + OFF_AL + off) = make_uint2(l0 | (l1 << 16), l2 | (l3 << 16));

            split_bf16(px[it].x, h0, l0); split_bf16(px[it].y, h1, l1);
            split_bf16(px[it].z, h2, l2); split_bf16(px[it].w, h3, l3);
            off = (unsigned)((bk + it * 8) * BPITCH * 2 + bg * 8);
            *(uint2*)(bp + OFF_BH + off) = make_uint2(h0 | (h1 << 16), h2 | (h3 << 16));
            *(uint2*)(bp + OFF_BL + off) = make_uint2(l0 | (l1 << 16), l2 | (l3 << 16));
        }
    };

    float acc[4][4][4];
    #pragma unroll
    for (int i = 0; i < 4; i++)
        #pragma unroll
        for (int j = 0; j < 4; j++)
            #pragma unroll
            for (int t = 0; t < 4; t++) acc[i][j][t] = 0.f;

    const int nch = K >> 5;

    // prologue
    load_chunk(0);
    store_chunk(0);
    load_chunk(1);
    __syncthreads();

    // ldmatrix lane addressing (constant across chunks except buffer base)
    const int lrow16 = lane & 15;          // row within 16 (A), k within 16 (B)
    const int khalf  = (lane >> 4) * 8;    // 0 or 8 (A k-block select)

    for (int c = 0; c < nch; c++) {
        const uint32_t bb = smb + (c & 1) * BUF_SZ;

        #pragma unroll
        for (int s = 0; s < 2; s++) {
            const int ks = s * 16;
            // B fragments: 4 n8 tiles, hi & lo
            uint32_t bhf[4][2], blf[4][2];
            const uint32_t brow = (uint32_t)((ks + lrow16) * BPITCH * 2);
            #pragma unroll
            for (int ni = 0; ni < 4; ni++) {
                const uint32_t bcol = (uint32_t)((wn + ni * 8) * 2);
                ldsm_x2_trans(bhf[ni], bb + OFF_BH + brow + bcol);
                ldsm_x2_trans(blf[ni], bb + OFF_BL + brow + bcol);
            }
            #pragma unroll
            for (int mi = 0; mi < 4; mi++) {
                uint32_t ah[4], al[4];
                const uint32_t aoff =
                    (uint32_t)((wm + mi * 16 + lrow16) * APITCH * 2 + (ks + khalf) * 2);
                ldsm_x4(ah, bb + OFF_AH + aoff);
                ldsm_x4(al, bb + OFF_AL + aoff);
                #pragma unroll
                for (int ni = 0; ni < 4; ni++) {
                    mma16816(acc[mi][ni], ah, bhf[ni]);
                    mma16816(acc[mi][ni], ah, blf[ni]);
                    mma16816(acc[mi][ni], al, bhf[ni]);
                }
            }
        }

        __syncthreads();
        if (c + 1 < nch) {
            store_chunk((c + 1) & 1);
            if (c + 2 < nch) load_chunk(c + 2);
            __syncthreads();
        }
    }

    // ---- epilogue: bias (+mask), direct global stores (float2, 32B sectors) ----
    const int r_in  = lane >> 2;           // 0..7
    const int c_in  = (lane & 3) * 2;      // 0,2,4,6
    #pragma unroll
    for (int mi = 0; mi < 4; mi++) {
        const int r0 = m0 + wm + mi * 16 + r_in;
        const float b0 = bias[r0];
        const float b1 = bias[r0 + 8];
        #pragma unroll
        for (int ni = 0; ni < 4; ni++) {
            const int col = n0 + wn + ni * 8 + c_in;
            float m0f = 1.f, m1f = 1.f;
            if (USE_MASK) {
                m0f = cmask[(size_t)bz * N + col];
                m1f = cmask[(size_t)bz * N + col + 1];
            }
            float2 v0, v1;
            v0.x = (acc[mi][ni][0] + b0) * (USE_MASK ? m0f : 1.f);
            v0.y = (acc[mi][ni][1] + b0) * (USE_MASK ? m1f : 1.f);
            v1.x = (acc[mi][ni][2] + b1) * (USE_MASK ? m0f : 1.f);
            v1.y = (acc[mi][ni][3] + b1) * (USE_MASK ? m1f : 1.f);
            *(float2*)(Cb + (size_t)r0 * N + col)       = v0;
            *(float2*)(Cb + (size_t)(r0 + 8) * N + col) = v1;
        }
    }
}

// ---------------------------------------------------------------------------
// Fused windowed attention per (window, head) CTA (unchanged — 332us measured)
// ---------------------------------------------------------------------------
#define ATTN_SMEM_FLOATS (128*128 + 128*68 + 128*16 + 128)
#define ATTN_SMEM_BYTES  (ATTN_SMEM_FLOATS * 4)

__device__ __forceinline__ float gelu_exact(float x) { return x * normcdff(x); }

__global__ __launch_bounds__(256, 2) void attn_kernel(const float* __restrict__ masks)
{
    extern __shared__ float smf[];
    float* qs    = smf;
    float* ks    = smf + 64 * 128;
    float* attnT = smf;                   // overlays qs+ks after scores
    float* vsT   = smf + 128 * 128;
    float* red   = vsT + 128 * 68;
    float* msk   = red + 128 * 16;

    const int tid = threadIdx.x;
    const int wh  = blockIdx.x;
    const int w   = wh >> 3;
    const int h   = wh & 7;
    const int b   = blockIdx.y;

    const size_t base = (size_t)b * DKK * SS + (size_t)h * DH * SS + (size_t)w * WW;

    #pragma unroll
    for (int r = 0; r < 8; r++) {
        int idx = tid + 256 * r;
        int d   = idx >> 5;
        int i4  = (idx & 31) << 2;
        size_t g = base + (size_t)d * SS + i4;
        float4 qv = *(const float4*)(g_Q + g);
        float4 kv = *(const float4*)(g_K + g);
        float4 vv = *(const float4*)(g_V + g);
        *(float4*)(qs + d * 128 + i4) = qv;
        *(float4*)(ks + d * 128 + i4) = kv;
        vsT[(i4 + 0) * 68 + d] = vv.x;
        vsT[(i4 + 1) * 68 + d] = vv.y;
        vsT[(i4 + 2) * 68 + d] = vv.z;
        vsT[(i4 + 3) * 68 + d] = vv.w;
    }
    if (tid < 32) {
        float4 mv = *(const float4*)(masks + (size_t)b * SS + w * WW + tid * 4);
        *(float4*)(msk + tid * 4) = mv;
    }
    __syncthreads();

    const int tx = tid & 15, ty = tid >> 4;
    const int i0 = ty * 8, j0 = tx * 8;

    float acc[8][8];
    #pragma unroll
    for (int u = 0; u < 8; u++)
        #pragma unroll
        for (int v = 0; v < 8; v++) acc[u][v] = 0.f;

    #pragma unroll 8
    for (int d = 0; d < DH; d++) {
        float ra[8], rb[8];
        *(float4*)(ra)     = *(const float4*)(qs + d * 128 + i0);
        *(float4*)(ra + 4) = *(const float4*)(qs + d * 128 + i0 + 4);
        *(float4*)(rb)     = *(const float4*)(ks + d * 128 + j0);
        *(float4*)(rb + 4) = *(const float4*)(ks + d * 128 + j0 + 4);
        #pragma unroll
        for (int u = 0; u < 8; u++)
            #pragma unroll
            for (int v = 0; v < 8; v++)
                acc[u][v] += ra[u] * rb[v];
    }

    float mj[8];
    #pragma unroll
    for (int v = 0; v < 8; v++) mj[v] = msk[j0 + v];
    #pragma unroll
    for (int u = 0; u < 8; u++)
        #pragma unroll
        for (int v = 0; v < 8; v++)
            acc[u][v] = (mj[v] > 0.f) ? acc[u][v] * 0.125f : -1e9f;

    #pragma unroll
    for (int u = 0; u < 8; u++) {
        float pm = acc[u][0];
        #pragma unroll
        for (int v = 1; v < 8; v++) pm = fmaxf(pm, acc[u][v]);
        red[(i0 + u) * 16 + tx] = pm;
    }
    __syncthreads();

    float rmax[8];
    #pragma unroll
    for (int u = 0; u < 8; u++) {
        float m = red[(i0 + u) * 16];
        #pragma unroll
        for (int t = 1; t < 16; t++) m = fmaxf(m, red[(i0 + u) * 16 + t]);
        rmax[u] = m;
    }
    __syncthreads();

    #pragma unroll
    for (int u = 0; u < 8; u++) {
        float s = 0.f;
        #pragma unroll
        for (int v = 0; v < 8; v++) {
            float e = expf(acc[u][v] - rmax[u]);
            acc[u][v] = e;
            s += e;
        }
        red[(i0 + u) * 16 + tx] = s;
    }
    __syncthreads();

    float inv[8];
    #pragma unroll
    for (int u = 0; u < 8; u++) {
        float s = 0.f;
        #pragma unroll
        for (int t = 0; t < 16; t++) s += red[(i0 + u) * 16 + t];
        inv[u] = 1.f / s;
    }

    #pragma unroll
    for (int v = 0; v < 8; v++) {
        float4 w0 = make_float4(acc[0][v] * inv[0], acc[1][v] * inv[1],
                                acc[2][v] * inv[2], acc[3][v] * inv[3]);
        float4 w1 = make_float4(acc[4][v] * inv[4], acc[5][v] * inv[5],
                                acc[6][v] * inv[6], acc[7][v] * inv[7]);
        *(float4*)(attnT + (j0 + v) * 128 + i0)     = w0;
        *(float4*)(attnT + (j0 + v) * 128 + i0 + 4) = w1;
    }
    __syncthreads();

    const int txa = tid & 15, tya = tid >> 4;
    const int ia  = txa * 8;
    const int d0  = tya * 4;

    float oacc[4][8];
    #pragma unroll
    for (int t = 0; t < 4; t++)
        #pragma unroll
        for (int u = 0; u < 8; u++) oacc[t][u] = 0.f;

    #pragma unroll 4
    for (int j = 0; j < 128; j++) {
        float a8[8], v4[4];
        *(float4*)(a8)     = *(const float4*)(attnT + j * 128 + ia);
        *(float4*)(a8 + 4) = *(const float4*)(attnT + j * 128 + ia + 4);
        *(float4*)(v4)     = *(const float4*)(vsT + j * 68 + d0);
        #pragma unroll
        for (int t = 0; t < 4; t++)
            #pragma unroll
            for (int u = 0; u < 8; u++)
                oacc[t][u] += v4[t] * a8[u];
    }

    #pragma unroll
    for (int t = 0; t < 4; t++) {
        size_t g = base + (size_t)(d0 + t) * SS + ia;
        float r[8];
        #pragma unroll
        for (int u = 0; u < 8; u++) r[u] = gelu_exact(oacc[t][u]);
        *(float4*)(g_O + g)     = *(float4*)(r);
        *(float4*)(g_O + g + 4) = *(float4*)(r + 4);
    }
}

// ---------------------------------------------------------------------------
extern "C" void kernel_launch(void* const* d_in, const int* in_sizes, int n_in,
                              void* d_out, int out_size)
{
    const float* qk    = (const float*)d_in[0];
    const float* v     = (const float*)d_in[1];
    const float* masks = (const float*)d_in[2];
    const float* Wq    = (const float*)d_in[3];
    const float* bq    = (const float*)d_in[4];
    const float* Wk    = (const float*)d_in[5];
    const float* bk    = (const float*)d_in[6];
    const float* Wv    = (const float*)d_in[7];
    const float* bv    = (const float*)d_in[8];
    const float* Wo    = (const float*)d_in[9];
    const float* bo    = (const float*)d_in[10];
    float* out = (float*)d_out;

    float *Q, *K, *V, *O;
    cudaGetSymbolAddress((void**)&Q, g_Q);
    cudaGetSymbolAddress((void**)&K, g_K);
    cudaGetSymbolAddress((void**)&V, g_V);
    cudaGetSymbolAddress((void**)&O, g_O);

    cudaFuncSetAttribute(gemm_mma<false>,
                         cudaFuncAttributeMaxDynamicSharedMemorySize, GSMEM_TOTAL);
    cudaFuncSetAttribute(gemm_mma<true>,
                         cudaFuncAttributeMaxDynamicSharedMemorySize, GSMEM_TOTAL);
    cudaFuncSetAttribute(attn_kernel,
                         cudaFuncAttributeMaxDynamicSharedMemorySize, ATTN_SMEM_BYTES);

    dim3 blk(256);
    // Q/K/V projections: [512,1024] x [1024,4096] per batch (mma.sync bf16x3)
    gemm_mma<false><<<dim3(32, 4, NB), blk, GSMEM_TOTAL>>>(Wq, qk, bq, nullptr, Q, DKK, SS, DD);
    gemm_mma<false><<<dim3(32, 4, NB), blk, GSMEM_TOTAL>>>(Wk, qk, bk, nullptr, K, DKK, SS, DD);
    gemm_mma<false><<<dim3(32, 4, NB), blk, GSMEM_TOTAL>>>(Wv, v,  bv, nullptr, V, DKK, SS, DD);

    // attention + GELU: one CTA per (window, head)
    attn_kernel<<<dim3(NWIN * NH, NB), blk, ATTN_SMEM_BYTES>>>(masks);

    // output projection + final mask: [1024,512] x [512,4096] per batch
    gemm_mma<true><<<dim3(32, 8, NB), blk, GSMEM_TOTAL>>>(Wo, O, bo, masks, out, DD, SS, DKK);
}

// round 6
// speedup vs baseline: 2.7738x; 1.6672x over previous
#include <cuda_runtime.h>
#include <cuda_fp16.h>
#include <math.h>
#include <stdint.h>

#define NB   8
#define SS   4096
#define DD   1024
#define DKK  512
#define NH   8
#define WW   128
#define DH   64
#define NWIN 32   // S / W

// fp32 scratch (attention I/O)
__device__ float g_Q[(size_t)NB * DKK * SS];
__device__ float g_K[(size_t)NB * DKK * SS];
__device__ float g_V[(size_t)NB * DKK * SS];
__device__ float g_O[(size_t)NB * DKK * SS];

// fp16 pre-converted operands
__device__ __half g_Bqk[(size_t)NB * DD * SS];    // qk -> fp16 (B operand, hi only)
__device__ __half g_Bv [(size_t)NB * DD * SS];    // v  -> fp16
__device__ __half g_Bo [(size_t)NB * DKK * SS];   // O  -> fp16
__device__ __half g_Wqh[DKK * DD], g_Wql[DKK * DD];
__device__ __half g_Wkh[DKK * DD], g_Wkl[DKK * DD];
__device__ __half g_Wvh[DKK * DD], g_Wvl[DKK * DD];
__device__ __half g_Woh[DD * DKK], g_Wol[DD * DKK];

// ============================================================================
// PTX helpers (sm_80+ only — compute_103-safe, no 'a' features)
// ============================================================================
__device__ __forceinline__ uint32_t smem_u32(const void* p) {
    uint32_t a;
    asm("{ .reg .u64 t; cvta.to.shared.u64 t, %1; cvt.u32.u64 %0, t; }"
        : "=r"(a) : "l"(p));
    return a;
}
__device__ __forceinline__ void ldsm_x4(uint32_t* r, uint32_t addr) {
    asm volatile("ldmatrix.sync.aligned.m8n8.x4.shared.b16 {%0,%1,%2,%3}, [%4];"
                 : "=r"(r[0]), "=r"(r[1]), "=r"(r[2]), "=r"(r[3]) : "r"(addr));
}
__device__ __forceinline__ void ldsm_x2_trans(uint32_t* r, uint32_t addr) {
    asm volatile("ldmatrix.sync.aligned.m8n8.x2.trans.shared.b16 {%0,%1}, [%2];"
                 : "=r"(r[0]), "=r"(r[1]) : "r"(addr));
}
__device__ __forceinline__ void mma16816(float* d, const uint32_t* a, const uint32_t* b) {
    asm volatile(
        "mma.sync.aligned.m16n8k16.row.col.f32.f16.f16.f32 "
        "{%0,%1,%2,%3},{%4,%5,%6,%7},{%8,%9},{%0,%1,%2,%3};"
        : "+f"(d[0]), "+f"(d[1]), "+f"(d[2]), "+f"(d[3])
        : "r"(a[0]), "r"(a[1]), "r"(a[2]), "r"(a[3]), "r"(b[0]), "r"(b[1]));
}
__device__ __forceinline__ void cp_async16(uint32_t dst, const void* src) {
    asm volatile("cp.async.cg.shared.global [%0], [%1], 16;" :: "r"(dst), "l"(src));
}
__device__ __forceinline__ void cp_commit() {
    asm volatile("cp.async.commit_group;" ::: "memory");
}
template<int N> __device__ __forceinline__ void cp_wait() {
    asm volatile("cp.async.wait_group %0;" :: "n"(N) : "memory");
}

// ============================================================================
// Conversion kernels (run once per buffer)
// ============================================================================
__global__ void cvt_hi(const float4* __restrict__ src, uint2* __restrict__ hi, int n4)
{
    int i = blockIdx.x * blockDim.x + threadIdx.x;
    if (i >= n4) return;
    float4 v = src[i];
    unsigned h0 = __half_as_ushort(__float2half_rn(v.x));
    unsigned h1 = __half_as_ushort(__float2half_rn(v.y));
    unsigned h2 = __half_as_ushort(__float2half_rn(v.z));
    unsigned h3 = __half_as_ushort(__float2half_rn(v.w));
    hi[i] = make_uint2(h0 | (h1 << 16), h2 | (h3 << 16));
}

__global__ void cvt_hilo(const float4* __restrict__ src,
                         uint2* __restrict__ hi, uint2* __restrict__ lo, int n4)
{
    int i = blockIdx.x * blockDim.x + threadIdx.x;
    if (i >= n4) return;
    float4 v = src[i];
    unsigned h[4], l[4];
    float x[4] = {v.x, v.y, v.z, v.w};
    #pragma unroll
    for (int t = 0; t < 4; t++) {
        __half bh = __float2half_rn(x[t]);
        __half bl = __float2half_rn(__fsub_rn(x[t], __half2float(bh)));
        h[t] = __half_as_ushort(bh);
        l[t] = __half_as_ushort(bl);
    }
    hi[i] = make_uint2(h[0] | (h[1] << 16), h[2] | (h[3] << 16));
    lo[i] = make_uint2(l[0] | (l[1] << 16), l[2] | (l[3] << 16));
}

// ============================================================================
// fp16x2 SGEMM via mma.sync + cp.async pipeline
//   C[bz] = (Ah+Al) @ Bh[bz] + bias (fp32 out), optional column mask
// A: [M,K] fp16 hi/lo (weights), B: [K,N] fp16 per batch, C: [M,N] fp32.
// CTA 128x128, 8 warps (2x4), warp tile 64x32, K-chunk 32, 3-stage cp.async.
// A smem pitch 40 elems (80B), B pitch 136 elems (272B) -> conflict-free LDSM.
// ============================================================================
#define OFF_AH   0
#define OFF_AL   10240                      // 128*80
#define OFF_BH   20480
#define STAGE_SZ 29184                      // + 32*272
#define NSTAGE   3
#define GSMEM_TOTAL (NSTAGE * STAGE_SZ)     // 87552

template<bool USE_MASK>
__global__ __launch_bounds__(256, 2) void gemm_fp16(
    const __half* __restrict__ Ah,
    const __half* __restrict__ Al,
    const __half* __restrict__ Bg,
    const float* __restrict__ bias,
    const float* __restrict__ cmask,
    float* __restrict__ C,
    int M, int N, int K)
{
    extern __shared__ char sm[];
    const int tid  = threadIdx.x;
    const int warp = tid >> 5;
    const int lane = tid & 31;
    const int bx = blockIdx.x, by = blockIdx.y, bz = blockIdx.z;
    const int n0 = bx * 128, m0 = by * 128;
    const int wm = (warp >> 2) * 64;
    const int wn = (warp & 3) * 32;

    const __half* Bb = Bg + (size_t)bz * K * N;
    float*        Cb = C  + (size_t)bz * M * N;
    const uint32_t smb = smem_u32(sm);

    // copy-index precompute
    const int ar = tid >> 2, aq = tid & 3;    // A: rows 0..63 (+64), 4x16B per row
    const int br = tid >> 4, bq = tid & 15;   // B: rows 0..15 (+16), 16x16B per row

    auto issue = [&](int c, int st) {
        const uint32_t sb = smb + st * STAGE_SZ;
        const __half* Ahp = Ah + (size_t)m0 * K + c * 32;
        const __half* Alp = Al + (size_t)m0 * K + c * 32;
        const __half* Bp  = Bb + (size_t)(c * 32) * N + n0;
        #pragma unroll
        for (int it = 0; it < 2; it++) {
            int r = ar + it * 64;
            uint32_t doff = (uint32_t)(r * 80 + aq * 16);
            cp_async16(sb + OFF_AH + doff, Ahp + (size_t)r * K + aq * 8);
            cp_async16(sb + OFF_AL + doff, Alp + (size_t)r * K + aq * 8);
            int rb = br + it * 16;
            cp_async16(sb + OFF_BH + (uint32_t)(rb * 272 + bq * 16),
                       Bp + (size_t)rb * N + bq * 8);
        }
    };

    float acc[4][4][4];
    #pragma unroll
    for (int i = 0; i < 4; i++)
        #pragma unroll
        for (int j = 0; j < 4; j++)
            #pragma unroll
            for (int t = 0; t < 4; t++) acc[i][j][t] = 0.f;

    const int nch = K >> 5;

    issue(0, 0); cp_commit();
    issue(1, 1); cp_commit();

    const int lrow16 = lane & 15;
    const int khalf  = (lane >> 4) * 8;

    for (int c = 0; c < nch; c++) {
        cp_wait<1>();
        __syncthreads();
        if (c + 2 < nch) issue(c + 2, (c + 2) % NSTAGE);
        cp_commit();   // unconditional (empty groups keep wait<1> arithmetic valid)

        const uint32_t bb = smb + (c % NSTAGE) * STAGE_SZ;
        #pragma unroll
        for (int s = 0; s < 2; s++) {
            const int ks = s * 16;
            uint32_t bhf[4][2];
            const uint32_t brow = (uint32_t)((ks + lrow16) * 272);
            #pragma unroll
            for (int ni = 0; ni < 4; ni++)
                ldsm_x2_trans(bhf[ni], bb + OFF_BH + brow + (uint32_t)((wn + ni * 8) * 2));
            #pragma unroll
            for (int mi = 0; mi < 4; mi++) {
                uint32_t ah[4], al[4];
                const uint32_t aoff =
                    (uint32_t)((wm + mi * 16 + lrow16) * 80 + (ks + khalf) * 2);
                ldsm_x4(ah, bb + OFF_AH + aoff);
                ldsm_x4(al, bb + OFF_AL + aoff);
                #pragma unroll
                for (int ni = 0; ni < 4; ni++) {
                    mma16816(acc[mi][ni], ah, bhf[ni]);
                    mma16816(acc[mi][ni], al, bhf[ni]);
                }
            }
        }
    }

    // epilogue: bias (+mask), float2 stores
    const int r_in = lane >> 2;
    const int c_in = (lane & 3) * 2;
    #pragma unroll
    for (int mi = 0; mi < 4; mi++) {
        const int r0 = m0 + wm + mi * 16 + r_in;
        const float b0 = bias[r0];
        const float b1 = bias[r0 + 8];
        #pragma unroll
        for (int ni = 0; ni < 4; ni++) {
            const int col = n0 + wn + ni * 8 + c_in;
            float m0f = 1.f, m1f = 1.f;
            if (USE_MASK) {
                m0f = cmask[(size_t)bz * N + col];
                m1f = cmask[(size_t)bz * N + col + 1];
            }
            float2 v0, v1;
            v0.x = (acc[mi][ni][0] + b0) * m0f;
            v0.y = (acc[mi][ni][1] + b0) * m1f;
            v1.x = (acc[mi][ni][2] + b1) * m0f;
            v1.y = (acc[mi][ni][3] + b1) * m1f;
            *(float2*)(Cb + (size_t)r0 * N + col)       = v0;
            *(float2*)(Cb + (size_t)(r0 + 8) * N + col) = v1;
        }
    }
}

// ---------------------------------------------------------------------------
// Fused windowed attention per (window, head) CTA (unchanged — 350us measured)
// ---------------------------------------------------------------------------
#define ATTN_SMEM_FLOATS (128*128 + 128*68 + 128*16 + 128)
#define ATTN_SMEM_BYTES  (ATTN_SMEM_FLOATS * 4)

__device__ __forceinline__ float gelu_exact(float x) { return x * normcdff(x); }

__global__ __launch_bounds__(256, 2) void attn_kernel(const float* __restrict__ masks)
{
    extern __shared__ float smf[];
    float* qs    = smf;
    float* ks    = smf + 64 * 128;
    float* attnT = smf;                   // overlays qs+ks after scores
    float* vsT   = smf + 128 * 128;
    float* red   = vsT + 128 * 68;
    float* msk   = red + 128 * 16;

    const int tid = threadIdx.x;
    const int wh  = blockIdx.x;
    const int w   = wh >> 3;
    const int h   = wh & 7;
    const int b   = blockIdx.y;

    const size_t base = (size_t)b * DKK * SS + (size_t)h * DH * SS + (size_t)w * WW;

    #pragma unroll
    for (int r = 0; r < 8; r++) {
        int idx = tid + 256 * r;
        int d   = idx >> 5;
        int i4  = (idx & 31) << 2;
        size_t g = base + (size_t)d * SS + i4;
        float4 qv = *(const float4*)(g_Q + g);
        float4 kv = *(const float4*)(g_K + g);
        float4 vv = *(const float4*)(g_V + g);
        *(float4*)(qs + d * 128 + i4) = qv;
        *(float4*)(ks + d * 128 + i4) = kv;
        vsT[(i4 + 0) * 68 + d] = vv.x;
        vsT[(i4 + 1) * 68 + d] = vv.y;
        vsT[(i4 + 2) * 68 + d] = vv.z;
        vsT[(i4 + 3) * 68 + d] = vv.w;
    }
    if (tid < 32) {
        float4 mv = *(const float4*)(masks + (size_t)b * SS + w * WW + tid * 4);
        *(float4*)(msk + tid * 4) = mv;
    }
    __syncthreads();

    const int tx = tid & 15, ty = tid >> 4;
    const int i0 = ty * 8, j0 = tx * 8;

    float acc[8][8];
    #pragma unroll
    for (int u = 0; u < 8; u++)
        #pragma unroll
        for (int v = 0; v < 8; v++) acc[u][v] = 0.f;

    #pragma unroll 8
    for (int d = 0; d < DH; d++) {
        float ra[8], rb[8];
        *(float4*)(ra)     = *(const float4*)(qs + d * 128 + i0);
        *(float4*)(ra + 4) = *(const float4*)(qs + d * 128 + i0 + 4);
        *(float4*)(rb)     = *(const float4*)(ks + d * 128 + j0);
        *(float4*)(rb + 4) = *(const float4*)(ks + d * 128 + j0 + 4);
        #pragma unroll
        for (int u = 0; u < 8; u++)
            #pragma unroll
            for (int v = 0; v < 8; v++)
                acc[u][v] += ra[u] * rb[v];
    }

    float mj[8];
    #pragma unroll
    for (int v = 0; v < 8; v++) mj[v] = msk[j0 + v];
    #pragma unroll
    for (int u = 0; u < 8; u++)
        #pragma unroll
        for (int v = 0; v < 8; v++)
            acc[u][v] = (mj[v] > 0.f) ? acc[u][v] * 0.125f : -1e9f;

    #pragma unroll
    for (int u = 0; u < 8; u++) {
        float pm = acc[u][0];
        #pragma unroll
        for (int v = 1; v < 8; v++) pm = fmaxf(pm, acc[u][v]);
        red[(i0 + u) * 16 + tx] = pm;
    }
    __syncthreads();

    float rmax[8];
    #pragma unroll
    for (int u = 0; u < 8; u++) {
        float m = red[(i0 + u) * 16];
        #pragma unroll
        for (int t = 1; t < 16; t++) m = fmaxf(m, red[(i0 + u) * 16 + t]);
        rmax[u] = m;
    }
    __syncthreads();

    #pragma unroll
    for (int u = 0; u < 8; u++) {
        float s = 0.f;
        #pragma unroll
        for (int v = 0; v < 8; v++) {
            float e = expf(acc[u][v] - rmax[u]);
            acc[u][v] = e;
            s += e;
        }
        red[(i0 + u) * 16 + tx] = s;
    }
    __syncthreads();

    float inv[8];
    #pragma unroll
    for (int u = 0; u < 8; u++) {
        float s = 0.f;
        #pragma unroll
        for (int t = 0; t < 16; t++) s += red[(i0 + u) * 16 + t];
        inv[u] = 1.f / s;
    }

    #pragma unroll
    for (int v = 0; v < 8; v++) {
        float4 w0 = make_float4(acc[0][v] * inv[0], acc[1][v] * inv[1],
                                acc[2][v] * inv[2], acc[3][v] * inv[3]);
        float4 w1 = make_float4(acc[4][v] * inv[4], acc[5][v] * inv[5],
                                acc[6][v] * inv[6], acc[7][v] * inv[7]);
        *(float4*)(attnT + (j0 + v) * 128 + i0)     = w0;
        *(float4*)(attnT + (j0 + v) * 128 + i0 + 4) = w1;
    }
    __syncthreads();

    const int txa = tid & 15, tya = tid >> 4;
    const int ia  = txa * 8;
    const int d0  = tya * 4;

    float oacc[4][8];
    #pragma unroll
    for (int t = 0; t < 4; t++)
        #pragma unroll
        for (int u = 0; u < 8; u++) oacc[t][u] = 0.f;

    #pragma unroll 4
    for (int j = 0; j < 128; j++) {
        float a8[8], v4[4];
        *(float4*)(a8)     = *(const float4*)(attnT + j * 128 + ia);
        *(float4*)(a8 + 4) = *(const float4*)(attnT + j * 128 + ia + 4);
        *(float4*)(v4)     = *(const float4*)(vsT + j * 68 + d0);
        #pragma unroll
        for (int t = 0; t < 4; t++)
            #pragma unroll
            for (int u = 0; u < 8; u++)
                oacc[t][u] += v4[t] * a8[u];
    }

    #pragma unroll
    for (int t = 0; t < 4; t++) {
        size_t g = base + (size_t)(d0 + t) * SS + ia;
        float r[8];
        #pragma unroll
        for (int u = 0; u < 8; u++) r[u] = gelu_exact(oacc[t][u]);
        *(float4*)(g_O + g)     = *(float4*)(r);
        *(float4*)(g_O + g + 4) = *(float4*)(r + 4);
    }
}

// ---------------------------------------------------------------------------
extern "C" void kernel_launch(void* const* d_in, const int* in_sizes, int n_in,
                              void* d_out, int out_size)
{
    const float* qk    = (const float*)d_in[0];
    const float* v     = (const float*)d_in[1];
    const float* masks = (const float*)d_in[2];
    const float* Wq    = (const float*)d_in[3];
    const float* bq    = (const float*)d_in[4];
    const float* Wk    = (const float*)d_in[5];
    const float* bk    = (const float*)d_in[6];
    const float* Wv    = (const float*)d_in[7];
    const float* bv    = (const float*)d_in[8];
    const float* Wo    = (const float*)d_in[9];
    const float* bo    = (const float*)d_in[10];
    float* out = (float*)d_out;

    float *Q, *K, *V, *O;
    cudaGetSymbolAddress((void**)&Q, g_Q);
    cudaGetSymbolAddress((void**)&K, g_K);
    cudaGetSymbolAddress((void**)&V, g_V);
    cudaGetSymbolAddress((void**)&O, g_O);
    __half *Bqk, *Bv, *Bo, *Wqh, *Wql, *Wkh, *Wkl, *Wvh, *Wvl, *Woh, *Wol;
    cudaGetSymbolAddress((void**)&Bqk, g_Bqk);
    cudaGetSymbolAddress((void**)&Bv,  g_Bv);
    cudaGetSymbolAddress((void**)&Bo,  g_Bo);
    cudaGetSymbolAddress((void**)&Wqh, g_Wqh); cudaGetSymbolAddress((void**)&Wql, g_Wql);
    cudaGetSymbolAddress((void**)&Wkh, g_Wkh); cudaGetSymbolAddress((void**)&Wkl, g_Wkl);
    cudaGetSymbolAddress((void**)&Wvh, g_Wvh); cudaGetSymbolAddress((void**)&Wvl, g_Wvl);
    cudaGetSymbolAddress((void**)&Woh, g_Woh); cudaGetSymbolAddress((void**)&Wol, g_Wol);

    cudaFuncSetAttribute(gemm_fp16<false>,
                         cudaFuncAttributeMaxDynamicSharedMemorySize, GSMEM_TOTAL);
    cudaFuncSetAttribute(gemm_fp16<true>,
                         cudaFuncAttributeMaxDynamicSharedMemorySize, GSMEM_TOTAL);
    cudaFuncSetAttribute(attn_kernel,
                         cudaFuncAttributeMaxDynamicSharedMemorySize, ATTN_SMEM_BYTES);

    dim3 blk(256);

    // ---- conversions ----
    const int nW = DKK * DD / 4;           // 131072 float4 per weight matrix
    cvt_hilo<<<nW / 256, blk>>>((const float4*)Wq, (uint2*)Wqh, (uint2*)Wql, nW);
    cvt_hilo<<<nW / 256, blk>>>((const float4*)Wk, (uint2*)Wkh, (uint2*)Wkl, nW);
    cvt_hilo<<<nW / 256, blk>>>((const float4*)Wv, (uint2*)Wvh, (uint2*)Wvl, nW);
    cvt_hilo<<<nW / 256, blk>>>((const float4*)Wo, (uint2*)Woh, (uint2*)Wol, nW);
    const int nX = NB * DD * SS / 4;       // 8.39M float4
    cvt_hi<<<nX / 256, blk>>>((const float4*)qk, (uint2*)Bqk, nX);
    cvt_hi<<<nX / 256, blk>>>((const float4*)v,  (uint2*)Bv,  nX);

    // ---- Q/K/V projections: [512,1024] x [1024,4096] per batch ----
    gemm_fp16<false><<<dim3(32, 4, NB), blk, GSMEM_TOTAL>>>(Wqh, Wql, Bqk, bq, nullptr, Q, DKK, SS, DD);
    gemm_fp16<false><<<dim3(32, 4, NB), blk, GSMEM_TOTAL>>>(Wkh, Wkl, Bqk, bk, nullptr, K, DKK, SS, DD);
    gemm_fp16<false><<<dim3(32, 4, NB), blk, GSMEM_TOTAL>>>(Wvh, Wvl, Bv,  bv, nullptr, V, DKK, SS, DD);

    // ---- attention + GELU ----
    attn_kernel<<<dim3(NWIN * NH, NB), blk, ATTN_SMEM_BYTES>>>(masks);

    // ---- convert O, then output projection + final mask ----
    const int nO = NB * DKK * SS / 4;
    cvt_hi<<<nO / 256, blk>>>((const float4*)O, (uint2*)Bo, nO);
    gemm_fp16<true><<<dim3(32, 8, NB), blk, GSMEM_TOTAL>>>(Woh, Wol, Bo, bo, masks, out, DD, SS, DKK);
}

// round 8
// speedup vs baseline: 3.3942x; 1.2237x over previous
#include <cuda_runtime.h>
#include <cuda_fp16.h>
#include <math.h>
#include <stdint.h>

#define NB   8
#define SS   4096
#define DD   1024
#define DKK  512
#define NH   8
#define WW   128
#define DH   64
#define NWIN 32   // S / W

// fp16 operand buffers (device globals: allowed)
__device__ __half g_Bqk[(size_t)NB * DD * SS];    // qk -> fp16 (GEMM B operand)
__device__ __half g_Bv [(size_t)NB * DD * SS];    // v  -> fp16
__device__ __half g_Bo [(size_t)NB * DKK * SS];   // GELU(attn out) fp16 (written by attn)
__device__ __half g_Qh[(size_t)NB * DKK * SS], g_Ql[(size_t)NB * DKK * SS];
__device__ __half g_Kh[(size_t)NB * DKK * SS], g_Kl[(size_t)NB * DKK * SS];
__device__ __half g_Vh[(size_t)NB * DKK * SS], g_Vl[(size_t)NB * DKK * SS];
__device__ __half g_Wqh[DKK * DD], g_Wql[DKK * DD];
__device__ __half g_Wkh[DKK * DD], g_Wkl[DKK * DD];
__device__ __half g_Wvh[DKK * DD], g_Wvl[DKK * DD];
__device__ __half g_Woh[DD * DKK], g_Wol[DD * DKK];

// ============================================================================
// PTX helpers (sm_80+ only — compute_103-safe)
// ============================================================================
__device__ __forceinline__ uint32_t smem_u32(const void* p) {
    uint32_t a;
    asm("{ .reg .u64 t; cvta.to.shared.u64 t, %1; cvt.u32.u64 %0, t; }"
        : "=r"(a) : "l"(p));
    return a;
}
__device__ __forceinline__ void ldsm_x4(uint32_t* r, uint32_t addr) {
    asm volatile("ldmatrix.sync.aligned.m8n8.x4.shared.b16 {%0,%1,%2,%3}, [%4];"
                 : "=r"(r[0]), "=r"(r[1]), "=r"(r[2]), "=r"(r[3]) : "r"(addr));
}
__device__ __forceinline__ void ldsm_x4_t(uint32_t* r, uint32_t addr) {
    asm volatile("ldmatrix.sync.aligned.m8n8.x4.trans.shared.b16 {%0,%1,%2,%3}, [%4];"
                 : "=r"(r[0]), "=r"(r[1]), "=r"(r[2]), "=r"(r[3]) : "r"(addr));
}
__device__ __forceinline__ void ldsm_x2_trans(uint32_t* r, uint32_t addr) {
    asm volatile("ldmatrix.sync.aligned.m8n8.x2.trans.shared.b16 {%0,%1}, [%2];"
                 : "=r"(r[0]), "=r"(r[1]) : "r"(addr));
}
__device__ __forceinline__ void mma16816(float* d, const uint32_t* a, const uint32_t* b) {
    asm volatile(
        "mma.sync.aligned.m16n8k16.row.col.f32.f16.f16.f32 "
        "{%0,%1,%2,%3},{%4,%5,%6,%7},{%8,%9},{%0,%1,%2,%3};"
        : "+f"(d[0]), "+f"(d[1]), "+f"(d[2]), "+f"(d[3])
        : "r"(a[0]), "r"(a[1]), "r"(a[2]), "r"(a[3]), "r"(b[0]), "r"(b[1]));
}
__device__ __forceinline__ void cp_async16(uint32_t dst, const void* src) {
    asm volatile("cp.async.cg.shared.global [%0], [%1], 16;" :: "r"(dst), "l"(src));
}
__device__ __forceinline__ void cp_commit() {
    asm volatile("cp.async.commit_group;" ::: "memory");
}
template<int N> __device__ __forceinline__ void cp_wait() {
    asm volatile("cp.async.wait_group %0;" :: "n"(N) : "memory");
}
__device__ __forceinline__ float gelu_exact(float x) { return x * normcdff(x); }

// ============================================================================
// Conversion kernels
// ============================================================================
__global__ void cvt_hi(const float4* __restrict__ src, uint2* __restrict__ hi, int n4)
{
    int i = blockIdx.x * blockDim.x + threadIdx.x;
    if (i >= n4) return;
    float4 v = src[i];
    unsigned h0 = __half_as_ushort(__float2half_rn(v.x));
    unsigned h1 = __half_as_ushort(__float2half_rn(v.y));
    unsigned h2 = __half_as_ushort(__float2half_rn(v.z));
    unsigned h3 = __half_as_ushort(__float2half_rn(v.w));
    hi[i] = make_uint2(h0 | (h1 << 16), h2 | (h3 << 16));
}

__global__ void cvt_hilo(const float4* __restrict__ src,
                         uint2* __restrict__ hi, uint2* __restrict__ lo, int n4)
{
    int i = blockIdx.x * blockDim.x + threadIdx.x;
    if (i >= n4) return;
    float4 v = src[i];
    unsigned h[4], l[4];
    float x[4] = {v.x, v.y, v.z, v.w};
    #pragma unroll
    for (int t = 0; t < 4; t++) {
        __half bh = __float2half_rn(x[t]);
        __half bl = __float2half_rn(__fsub_rn(x[t], __half2float(bh)));
        h[t] = __half_as_ushort(bh);
        l[t] = __half_as_ushort(bl);
    }
    hi[i] = make_uint2(h[0] | (h[1] << 16), h[2] | (h[3] << 16));
    lo[i] = make_uint2(l[0] | (l[1] << 16), l[2] | (l[3] << 16));
}

// ============================================================================
// fp16x2 GEMM via mma.sync + cp.async:  C[bz] = (Ah+Al) @ B[bz] + bias
// HILO=true : write hi/lo fp16 outputs (QKV projections, no mask)
// HILO=false: write fp32 output with column mask (final projection)
// ============================================================================
#define OFF_AH   0
#define OFF_AL   10240
#define OFF_BH   20480
#define STAGE_SZ 29184
#define NSTAGE   3
#define GSMEM_TOTAL (NSTAGE * STAGE_SZ)

template<bool HILO>
__global__ __launch_bounds__(256, 2) void gemm_fp16(
    const __half* __restrict__ Ah,
    const __half* __restrict__ Al,
    const __half* __restrict__ Bg,
    const float* __restrict__ bias,
    const float* __restrict__ cmask,
    float* __restrict__ C,
    __half* __restrict__ Ch,
    __half* __restrict__ Cl,
    int M, int N, int K)
{
    extern __shared__ char sm[];
    const int tid  = threadIdx.x;
    const int warp = tid >> 5;
    const int lane = tid & 31;
    const int bx = blockIdx.x, by = blockIdx.y, bz = blockIdx.z;
    const int n0 = bx * 128, m0 = by * 128;
    const int wm = (warp >> 2) * 64;
    const int wn = (warp & 3) * 32;

    const __half* Bb = Bg + (size_t)bz * K * N;
    const uint32_t smb = smem_u32(sm);

    const int ar = tid >> 2, aq = tid & 3;
    const int br = tid >> 4, bq = tid & 15;

    auto issue = [&](int c, int st) {
        const uint32_t sb = smb + st * STAGE_SZ;
        const __half* Ahp = Ah + (size_t)m0 * K + c * 32;
        const __half* Alp = Al + (size_t)m0 * K + c * 32;
        const __half* Bp  = Bb + (size_t)(c * 32) * N + n0;
        #pragma unroll
        for (int it = 0; it < 2; it++) {
            int r = ar + it * 64;
            uint32_t doff = (uint32_t)(r * 80 + aq * 16);
            cp_async16(sb + OFF_AH + doff, Ahp + (size_t)r * K + aq * 8);
            cp_async16(sb + OFF_AL + doff, Alp + (size_t)r * K + aq * 8);
            int rb = br + it * 16;
            cp_async16(sb + OFF_BH + (uint32_t)(rb * 272 + bq * 16),
                       Bp + (size_t)rb * N + bq * 8);
        }
    };

    float acc[4][4][4];
    #pragma unroll
    for (int i = 0; i < 4; i++)
        #pragma unroll
        for (int j = 0; j < 4; j++)
            #pragma unroll
            for (int t = 0; t < 4; t++) acc[i][j][t] = 0.f;

    const int nch = K >> 5;

    issue(0, 0); cp_commit();
    issue(1, 1); cp_commit();

    const int lrow16 = lane & 15;
    const int khalf  = (lane >> 4) * 8;

    for (int c = 0; c < nch; c++) {
        cp_wait<1>();
        __syncthreads();
        if (c + 2 < nch) issue(c + 2, (c + 2) % NSTAGE);
        cp_commit();

        const uint32_t bb = smb + (c % NSTAGE) * STAGE_SZ;
        #pragma unroll
        for (int s = 0; s < 2; s++) {
            const int ks = s * 16;
            uint32_t bhf[4][2];
            const uint32_t brow = (uint32_t)((ks + lrow16) * 272);
            #pragma unroll
            for (int ni = 0; ni < 4; ni++)
                ldsm_x2_trans(bhf[ni], bb + OFF_BH + brow + (uint32_t)((wn + ni * 8) * 2));
            #pragma unroll
            for (int mi = 0; mi < 4; mi++) {
                uint32_t ah[4], al[4];
                const uint32_t aoff =
                    (uint32_t)((wm + mi * 16 + lrow16) * 80 + (ks + khalf) * 2);
                ldsm_x4(ah, bb + OFF_AH + aoff);
                ldsm_x4(al, bb + OFF_AL + aoff);
                #pragma unroll
                for (int ni = 0; ni < 4; ni++) {
                    mma16816(acc[mi][ni], ah, bhf[ni]);
                    mma16816(acc[mi][ni], al, bhf[ni]);
                }
            }
        }
    }

    const int r_in = lane >> 2;
    const int c_in = (lane & 3) * 2;
    // batch bases for outputs (THE R6 BUG: HILO stores lacked bz offset)
    __half* Chb = HILO ? (Ch + (size_t)bz * M * N) : nullptr;
    __half* Clb = HILO ? (Cl + (size_t)bz * M * N) : nullptr;
    float*  Cb  = HILO ? nullptr : (C + (size_t)bz * M * N);

    #pragma unroll
    for (int mi = 0; mi < 4; mi++) {
        const int r0 = m0 + wm + mi * 16 + r_in;
        const float b0 = bias[r0];
        const float b1 = bias[r0 + 8];
        #pragma unroll
        for (int ni = 0; ni < 4; ni++) {
            const int col = n0 + wn + ni * 8 + c_in;
            float v0 = acc[mi][ni][0] + b0, v1 = acc[mi][ni][1] + b0;
            float v2 = acc[mi][ni][2] + b1, v3 = acc[mi][ni][3] + b1;
            if (HILO) {
                __half h0 = __float2half_rn(v0), h1 = __float2half_rn(v1);
                __half h2 = __float2half_rn(v2), h3 = __float2half_rn(v3);
                __half l0 = __float2half_rn(__fsub_rn(v0, __half2float(h0)));
                __half l1 = __float2half_rn(__fsub_rn(v1, __half2float(h1)));
                __half l2 = __float2half_rn(__fsub_rn(v2, __half2float(h2)));
                __half l3 = __float2half_rn(__fsub_rn(v3, __half2float(h3)));
                *(__half2*)(Chb + (size_t)r0 * N + col)       = __halves2half2(h0, h1);
                *(__half2*)(Clb + (size_t)r0 * N + col)       = __halves2half2(l0, l1);
                *(__half2*)(Chb + (size_t)(r0 + 8) * N + col) = __halves2half2(h2, h3);
                *(__half2*)(Clb + (size_t)(r0 + 8) * N + col) = __halves2half2(l2, l3);
            } else {
                float m0f = cmask[(size_t)bz * N + col];
                float m1f = cmask[(size_t)bz * N + col + 1];
                *(float2*)(Cb + (size_t)r0 * N + col)       = make_float2(v0 * m0f, v1 * m1f);
                *(float2*)(Cb + (size_t)(r0 + 8) * N + col) = make_float2(v2 * m0f, v3 * m1f);
            }
        }
    }
}

// ============================================================================
// Tensor-core windowed attention: one CTA per (window, head, batch).
// QK^T (3-pass hi/lo) -> warp-local softmax -> P hi/lo -> AV (3-pass) ->
// /sum, exact GELU, write g_Bo fp16.
// smem tiles pitch 136 halfs (272B) — conflict-free for all ldmatrix phases.
// ============================================================================
#define AT_QH  0
#define AT_QL  17408
#define AT_KH  34816
#define AT_KL  52224
#define AT_VH  69632
#define AT_VL  87040
#define AT_PH  0        // overlays QH+QL after QK phase
#define AT_PL  34816    // overlays KH+KL
#define AT_SUM 104448   // float[128]
#define AT_MSK 104960   // float[128]
#define AT_SMEM 105472

__global__ __launch_bounds__(256, 2) void attn_mma(const float* __restrict__ masks)
{
    extern __shared__ char sm[];
    const uint32_t smb = smem_u32(sm);
    const int tid = threadIdx.x, warp = tid >> 5, lane = tid & 31;
    const int wh = blockIdx.x, w = wh >> 3, h = wh & 7, b = blockIdx.y;
    const size_t base = ((size_t)b * DKK + h * 64) * SS + (size_t)w * WW;

    // ---- load 6 tiles [64][128] fp16 into smem (pitch 272B) ----
    {
        const __half* srcs[6] = { g_Qh + base, g_Ql + base, g_Kh + base,
                                  g_Kl + base, g_Vh + base, g_Vl + base };
        #pragma unroll
        for (int t = 0; t < 6; t++) {
            const uint32_t dstb = smb + t * 17408;
            #pragma unroll
            for (int it = 0; it < 4; it++) {
                int idx = tid + it * 256;
                int row = idx >> 4, ch = idx & 15;
                cp_async16(dstb + row * 272 + ch * 16,
                           srcs[t] + (size_t)row * SS + ch * 8);
            }
        }
        cp_commit();
    }
    if (tid < 32) {
        float4 mv = *(const float4*)(masks + (size_t)b * SS + w * WW + tid * 4);
        *(float4*)(sm + AT_MSK + tid * 16) = mv;
    }
    cp_wait<0>();
    __syncthreads();

    const int r_in = lane >> 2, c_in = (lane & 3) * 2;
    const uint32_t l7 = lane & 7, mh = (lane >> 3) & 1, kh = (lane >> 4) & 1;
    const int i0w = warp * 16;     // this warp's 16 score rows

    // ---- QK^T: acc[f][4], f over 16 n8 col-tiles (j = 0..127) ----
    float acc[16][4];
    #pragma unroll
    for (int f = 0; f < 16; f++)
        #pragma unroll
        for (int t = 0; t < 4; t++) acc[f][t] = 0.f;

    #pragma unroll
    for (int s = 0; s < 4; s++) {            // k = d, 16 per step
        uint32_t ah[4], al[4];
        const uint32_t aaddr = smb + (s * 16 + kh * 8 + l7) * 272 + (i0w + mh * 8) * 2;
        ldsm_x4_t(ah, aaddr + AT_QH);
        ldsm_x4_t(al, aaddr + AT_QL);
        #pragma unroll
        for (int q = 0; q < 8; q++) {        // each q covers 2 n8 tiles (16 j)
            const uint32_t baddr = smb + AT_KH +
                (s * 16 + mh * 8 + l7) * 272 + (q * 16 + kh * 8) * 2;
            uint32_t bh4[4], bl4[4];
            ldsm_x4_t(bh4, baddr);
            ldsm_x4_t(bl4, baddr + (AT_KL - AT_KH));
            const int f0 = q * 2;
            mma16816(acc[f0],     ah, bh4);
            mma16816(acc[f0],     al, bh4);
            mma16816(acc[f0],     ah, bl4);
            mma16816(acc[f0 + 1], ah, bh4 + 2);
            mma16816(acc[f0 + 1], al, bh4 + 2);
            mma16816(acc[f0 + 1], ah, bl4 + 2);
        }
    }

    // ---- mask + scale + warp-local softmax (rows r_in, r_in+8) ----
    const float* mk = (const float*)(sm + AT_MSK);
    float mx0 = -1e30f, mx1 = -1e30f;
    #pragma unroll
    for (int f = 0; f < 16; f++) {
        const int j = f * 8 + c_in;
        const float mj0 = mk[j], mj1 = mk[j + 1];
        acc[f][0] = (mj0 > 0.f) ? acc[f][0] * 0.125f : -1e9f;
        acc[f][1] = (mj1 > 0.f) ? acc[f][1] * 0.125f : -1e9f;
        acc[f][2] = (mj0 > 0.f) ? acc[f][2] * 0.125f : -1e9f;
        acc[f][3] = (mj1 > 0.f) ? acc[f][3] * 0.125f : -1e9f;
        mx0 = fmaxf(mx0, fmaxf(acc[f][0], acc[f][1]));
        mx1 = fmaxf(mx1, fmaxf(acc[f][2], acc[f][3]));
    }
    mx0 = fmaxf(mx0, __shfl_xor_sync(0xffffffffu, mx0, 1));
    mx0 = fmaxf(mx0, __shfl_xor_sync(0xffffffffu, mx0, 2));
    mx1 = fmaxf(mx1, __shfl_xor_sync(0xffffffffu, mx1, 1));
    mx1 = fmaxf(mx1, __shfl_xor_sync(0xffffffffu, mx1, 2));

    float s0 = 0.f, s1 = 0.f;
    #pragma unroll
    for (int f = 0; f < 16; f++) {
        acc[f][0] = __expf(acc[f][0] - mx0);
        acc[f][1] = __expf(acc[f][1] - mx0);
        acc[f][2] = __expf(acc[f][2] - mx1);
        acc[f][3] = __expf(acc[f][3] - mx1);
        s0 += acc[f][0] + acc[f][1];
        s1 += acc[f][2] + acc[f][3];
    }
    s0 += __shfl_xor_sync(0xffffffffu, s0, 1);
    s0 += __shfl_xor_sync(0xffffffffu, s0, 2);
    s1 += __shfl_xor_sync(0xffffffffu, s1, 1);
    s1 += __shfl_xor_sync(0xffffffffu, s1, 2);
    if ((lane & 3) == 0) {
        ((float*)(sm + AT_SUM))[i0w + r_in]     = s0;
        ((float*)(sm + AT_SUM))[i0w + r_in + 8] = s1;
    }

    __syncthreads();   // all QK smem reads done -> safe to overlay P

    // ---- store P^T hi/lo: sP[j][i], pitch 272B ----
    #pragma unroll
    for (int f = 0; f < 16; f++) {
        const int j = f * 8 + c_in;
        const int i = i0w + r_in;
        #pragma unroll
        for (int t = 0; t < 4; t++) {
            const int jj = j + (t & 1);
            const int ii = i + (t >> 1) * 8;
            const float p = acc[f][t];
            const __half ph = __float2half_rn(p);
            const __half pl = __float2half_rn(__fsub_rn(p, __half2float(ph)));
            *(__half*)(sm + AT_PH + (jj * 136 + ii) * 2) = ph;
            *(__half*)(sm + AT_PL + (jj * 136 + ii) * 2) = pl;
        }
    }
    __syncthreads();

    // ---- AV: O[d][i] = V @ P^T, warp grid 2(m=d) x 4(n=i), tile 32x32 ----
    const int wam = (warp >> 2) * 32, wan = (warp & 3) * 32;
    float oc[2][4][4];
    #pragma unroll
    for (int mi = 0; mi < 2; mi++)
        #pragma unroll
        for (int ni = 0; ni < 4; ni++)
            #pragma unroll
            for (int t = 0; t < 4; t++) oc[mi][ni][t] = 0.f;

    #pragma unroll
    for (int s = 0; s < 8; s++) {            // k = j, 16 per step
        uint32_t avh[2][4], avl[2][4];
        #pragma unroll
        for (int mi = 0; mi < 2; mi++) {
            const uint32_t aaddr = smb + AT_VH +
                (wam + mi * 16 + (lane & 15)) * 272 + (s * 16 + (lane >> 4) * 8) * 2;
            ldsm_x4(avh[mi], aaddr);
            ldsm_x4(avl[mi], aaddr + (AT_VL - AT_VH));
        }
        #pragma unroll
        for (int q = 0; q < 2; q++) {        // each q covers 2 n8 tiles
            const uint32_t baddr = smb + AT_PH +
                (s * 16 + mh * 8 + l7) * 272 + (wan + q * 16 + kh * 8) * 2;
            uint32_t bph[4], bpl[4];
            ldsm_x4_t(bph, baddr);
            ldsm_x4_t(bpl, baddr + (AT_PL - AT_PH));
            #pragma unroll
            for (int mi = 0; mi < 2; mi++) {
                const int n0f = q * 2;
                mma16816(oc[mi][n0f],     avh[mi], bph);
                mma16816(oc[mi][n0f],     avl[mi], bph);
                mma16816(oc[mi][n0f],     avh[mi], bpl);
                mma16816(oc[mi][n0f + 1], avh[mi], bph + 2);
                mma16816(oc[mi][n0f + 1], avl[mi], bph + 2);
                mma16816(oc[mi][n0f + 1], avh[mi], bpl + 2);
            }
        }
    }

    // ---- epilogue: /sum, exact GELU, fp16 store to g_Bo ----
    const float* sums = (const float*)(sm + AT_SUM);
    #pragma unroll
    for (int mi = 0; mi < 2; mi++) {
        const int d = wam + mi * 16 + r_in;
        #pragma unroll
        for (int ni = 0; ni < 4; ni++) {
            const int i = wan + ni * 8 + c_in;
            const float inv0 = 1.f / sums[i];
            const float inv1 = 1.f / sums[i + 1];
            const float o0 = gelu_exact(oc[mi][ni][0] * inv0);
            const float o1 = gelu_exact(oc[mi][ni][1] * inv1);
            const float o2 = gelu_exact(oc[mi][ni][2] * inv0);
            const float o3 = gelu_exact(oc[mi][ni][3] * inv1);
            const size_t g = base + (size_t)d * SS + i;
            *(__half2*)(g_Bo + g)          = __halves2half2(__float2half_rn(o0), __float2half_rn(o1));
            *(__half2*)(g_Bo + g + 8 * SS) = __halves2half2(__float2half_rn(o2), __float2half_rn(o3));
        }
    }
}

// ---------------------------------------------------------------------------
extern "C" void kernel_launch(void* const* d_in, const int* in_sizes, int n_in,
                              void* d_out, int out_size)
{
    const float* qk    = (const float*)d_in[0];
    const float* v     = (const float*)d_in[1];
    const float* masks = (const float*)d_in[2];
    const float* Wq    = (const float*)d_in[3];
    const float* bq    = (const float*)d_in[4];
    const float* Wk    = (const float*)d_in[5];
    const float* bk    = (const float*)d_in[6];
    const float* Wv    = (const float*)d_in[7];
    const float* bv    = (const float*)d_in[8];
    const float* Wo    = (const float*)d_in[9];
    const float* bo    = (const float*)d_in[10];
    float* out = (float*)d_out;

    __half *Bqk, *Bv, *Bo, *Qh, *Ql, *Kh, *Kl, *Vh, *Vl;
    __half *Wqh, *Wql, *Wkh, *Wkl, *Wvh, *Wvl, *Woh, *Wol;
    cudaGetSymbolAddress((void**)&Bqk, g_Bqk);
    cudaGetSymbolAddress((void**)&Bv,  g_Bv);
    cudaGetSymbolAddress((void**)&Bo,  g_Bo);
    cudaGetSymbolAddress((void**)&Qh, g_Qh); cudaGetSymbolAddress((void**)&Ql, g_Ql);
    cudaGetSymbolAddress((void**)&Kh, g_Kh); cudaGetSymbolAddress((void**)&Kl, g_Kl);
    cudaGetSymbolAddress((void**)&Vh, g_Vh); cudaGetSymbolAddress((void**)&Vl, g_Vl);
    cudaGetSymbolAddress((void**)&Wqh, g_Wqh); cudaGetSymbolAddress((void**)&Wql, g_Wql);
    cudaGetSymbolAddress((void**)&Wkh, g_Wkh); cudaGetSymbolAddress((void**)&Wkl, g_Wkl);
    cudaGetSymbolAddress((void**)&Wvh, g_Wvh); cudaGetSymbolAddress((void**)&Wvl, g_Wvl);
    cudaGetSymbolAddress((void**)&Woh, g_Woh); cudaGetSymbolAddress((void**)&Wol, g_Wol);

    cudaFuncSetAttribute(gemm_fp16<true>,
                         cudaFuncAttributeMaxDynamicSharedMemorySize, GSMEM_TOTAL);
    cudaFuncSetAttribute(gemm_fp16<false>,
                         cudaFuncAttributeMaxDynamicSharedMemorySize, GSMEM_TOTAL);
    cudaFuncSetAttribute(attn_mma,
                         cudaFuncAttributeMaxDynamicSharedMemorySize, AT_SMEM);

    dim3 blk(256);

    // ---- conversions ----
    const int nW = DKK * DD / 4;
    cvt_hilo<<<nW / 256, blk>>>((const float4*)Wq, (uint2*)Wqh, (uint2*)Wql, nW);
    cvt_hilo<<<nW / 256, blk>>>((const float4*)Wk, (uint2*)Wkh, (uint2*)Wkl, nW);
    cvt_hilo<<<nW / 256, blk>>>((const float4*)Wv, (uint2*)Wvh, (uint2*)Wvl, nW);
    cvt_hilo<<<nW / 256, blk>>>((const float4*)Wo, (uint2*)Woh, (uint2*)Wol, nW);
    const int nX = NB * DD * SS / 4;
    cvt_hi<<<nX / 256, blk>>>((const float4*)qk, (uint2*)Bqk, nX);
    cvt_hi<<<nX / 256, blk>>>((const float4*)v,  (uint2*)Bv,  nX);

    // ---- Q/K/V projections (write fp16 hi/lo directly) ----
    gemm_fp16<true><<<dim3(32, 4, NB), blk, GSMEM_TOTAL>>>(
        Wqh, Wql, Bqk, bq, nullptr, nullptr, Qh, Ql, DKK, SS, DD);
    gemm_fp16<true><<<dim3(32, 4, NB), blk, GSMEM_TOTAL>>>(
        Wkh, Wkl, Bqk, bk, nullptr, nullptr, Kh, Kl, DKK, SS, DD);
    gemm_fp16<true><<<dim3(32, 4, NB), blk, GSMEM_TOTAL>>>(
        Wvh, Wvl, Bv, bv, nullptr, nullptr, Vh, Vl, DKK, SS, DD);

    // ---- tensor-core attention + GELU (writes g_Bo fp16) ----
    attn_mma<<<dim3(NWIN * NH, NB), blk, AT_SMEM>>>(masks);

    // ---- output projection + final mask (fp32 out) ----
    gemm_fp16<false><<<dim3(32, 8, NB), blk, GSMEM_TOTAL>>>(
        Woh, Wol, Bo, bo, masks, out, nullptr, nullptr, DD, SS, DKK);
}

// round 9
// speedup vs baseline: 3.7276x; 1.0982x over previous
#include <cuda_runtime.h>
#include <cuda_fp16.h>
#include <math.h>
#include <stdint.h>

#define NB   8
#define SS   4096
#define DD   1024
#define DKK  512
#define NH   8
#define WW   128
#define DH   64
#define NWIN 32   // S / W

// fp16 operand buffers (device globals: allowed)
__device__ __half g_Bqk[(size_t)NB * DD * SS];    // qk -> fp16 (GEMM B operand)
__device__ __half g_Bv [(size_t)NB * DD * SS];    // v  -> fp16
__device__ __half g_Bo [(size_t)NB * DKK * SS];   // GELU(attn out) fp16 (written by attn)
__device__ __half g_Qh[(size_t)NB * DKK * SS], g_Ql[(size_t)NB * DKK * SS];
__device__ __half g_Kh[(size_t)NB * DKK * SS], g_Kl[(size_t)NB * DKK * SS];
__device__ __half g_Vh[(size_t)NB * DKK * SS], g_Vl[(size_t)NB * DKK * SS];
__device__ __half g_Wqh[DKK * DD], g_Wql[DKK * DD];
__device__ __half g_Wkh[DKK * DD], g_Wkl[DKK * DD];
__device__ __half g_Wvh[DKK * DD], g_Wvl[DKK * DD];
__device__ __half g_Woh[DD * DKK], g_Wol[DD * DKK];

// ============================================================================
// PTX helpers (sm_80+ only — compute_103-safe)
// ============================================================================
__device__ __forceinline__ uint32_t smem_u32(const void* p) {
    uint32_t a;
    asm("{ .reg .u64 t; cvta.to.shared.u64 t, %1; cvt.u32.u64 %0, t; }"
        : "=r"(a) : "l"(p));
    return a;
}
__device__ __forceinline__ void ldsm_x4(uint32_t* r, uint32_t addr) {
    asm volatile("ldmatrix.sync.aligned.m8n8.x4.shared.b16 {%0,%1,%2,%3}, [%4];"
                 : "=r"(r[0]), "=r"(r[1]), "=r"(r[2]), "=r"(r[3]) : "r"(addr));
}
__device__ __forceinline__ void ldsm_x4_t(uint32_t* r, uint32_t addr) {
    asm volatile("ldmatrix.sync.aligned.m8n8.x4.trans.shared.b16 {%0,%1,%2,%3}, [%4];"
                 : "=r"(r[0]), "=r"(r[1]), "=r"(r[2]), "=r"(r[3]) : "r"(addr));
}
__device__ __forceinline__ void mma16816(float* d, const uint32_t* a, const uint32_t* b) {
    asm volatile(
        "mma.sync.aligned.m16n8k16.row.col.f32.f16.f16.f32 "
        "{%0,%1,%2,%3},{%4,%5,%6,%7},{%8,%9},{%0,%1,%2,%3};"
        : "+f"(d[0]), "+f"(d[1]), "+f"(d[2]), "+f"(d[3])
        : "r"(a[0]), "r"(a[1]), "r"(a[2]), "r"(a[3]), "r"(b[0]), "r"(b[1]));
}
__device__ __forceinline__ void cp_async16(uint32_t dst, const void* src) {
    asm volatile("cp.async.cg.shared.global [%0], [%1], 16;" :: "r"(dst), "l"(src));
}
__device__ __forceinline__ void cp_commit() {
    asm volatile("cp.async.commit_group;" ::: "memory");
}
template<int N> __device__ __forceinline__ void cp_wait() {
    asm volatile("cp.async.wait_group %0;" :: "n"(N) : "memory");
}
__device__ __forceinline__ float gelu_exact(float x) { return x * normcdff(x); }

// ============================================================================
// Conversion kernels
// ============================================================================
__global__ void cvt_hi(const float4* __restrict__ src, uint2* __restrict__ hi, int n4)
{
    int i = blockIdx.x * blockDim.x + threadIdx.x;
    if (i >= n4) return;
    float4 v = src[i];
    unsigned h0 = __half_as_ushort(__float2half_rn(v.x));
    unsigned h1 = __half_as_ushort(__float2half_rn(v.y));
    unsigned h2 = __half_as_ushort(__float2half_rn(v.z));
    unsigned h3 = __half_as_ushort(__float2half_rn(v.w));
    hi[i] = make_uint2(h0 | (h1 << 16), h2 | (h3 << 16));
}

__global__ void cvt_hilo(const float4* __restrict__ src,
                         uint2* __restrict__ hi, uint2* __restrict__ lo, int n4)
{
    int i = blockIdx.x * blockDim.x + threadIdx.x;
    if (i >= n4) return;
    float4 v = src[i];
    unsigned h[4], l[4];
    float x[4] = {v.x, v.y, v.z, v.w};
    #pragma unroll
    for (int t = 0; t < 4; t++) {
        __half bh = __float2half_rn(x[t]);
        __half bl = __float2half_rn(__fsub_rn(x[t], __half2float(bh)));
        h[t] = __half_as_ushort(bh);
        l[t] = __half_as_ushort(bl);
    }
    hi[i] = make_uint2(h[0] | (h[1] << 16), h[2] | (h[3] << 16));
    lo[i] = make_uint2(l[0] | (l[1] << 16), l[2] | (l[3] << 16));
}

// ============================================================================
// fp16 GEMM via mma.sync + cp.async:  C[bz] = A @ B[bz] + bias
// TWOPASS: A = Ah + Al (two MMA passes); else single fp16 A (final proj).
// HILO=true : write hi/lo fp16 outputs (QKV projections, no mask)
// HILO=false: write fp32 output with column mask (final projection)
// CTA 128x128, warp grid 4(m) x 2(n), warp tile 32x64, K-chunk 32, 3 stages.
// A smem [m][k] pitch 80B, B smem [k][n] pitch 272B — conflict-free ldmatrix.
// ============================================================================
#define OFF_AH   0
#define OFF_AL   10240
#define OFF_BH   20480
#define STAGE_SZ 29184
#define NSTAGE   3
#define GSMEM_TOTAL (NSTAGE * STAGE_SZ)

template<bool HILO, bool TWOPASS>
__global__ __launch_bounds__(256, 2) void gemm_fp16(
    const __half* __restrict__ Ah,
    const __half* __restrict__ Al,
    const __half* __restrict__ Bg,
    const float* __restrict__ bias,
    const float* __restrict__ cmask,
    float* __restrict__ C,
    __half* __restrict__ Ch,
    __half* __restrict__ Cl,
    int M, int N, int K)
{
    extern __shared__ char sm[];
    const int tid  = threadIdx.x;
    const int warp = tid >> 5;
    const int lane = tid & 31;
    const int bx = blockIdx.x, by = blockIdx.y, bz = blockIdx.z;
    const int n0 = bx * 128, m0 = by * 128;
    const int wm = (warp >> 1) * 32;     // 4 m-groups of 32
    const int wn = (warp & 1) * 64;      // 2 n-groups of 64

    const __half* Bb = Bg + (size_t)bz * K * N;
    const uint32_t smb = smem_u32(sm);

    const int ar = tid >> 2, aq = tid & 3;
    const int br = tid >> 4, bq = tid & 15;

    auto issue = [&](int c, int st) {
        const uint32_t sb = smb + st * STAGE_SZ;
        const __half* Ahp = Ah + (size_t)m0 * K + c * 32;
        const __half* Bp  = Bb + (size_t)(c * 32) * N + n0;
        #pragma unroll
        for (int it = 0; it < 2; it++) {
            int r = ar + it * 64;
            uint32_t doff = (uint32_t)(r * 80 + aq * 16);
            cp_async16(sb + OFF_AH + doff, Ahp + (size_t)r * K + aq * 8);
            if (TWOPASS) {
                const __half* Alp = Al + (size_t)m0 * K + c * 32;
                cp_async16(sb + OFF_AL + doff, Alp + (size_t)r * K + aq * 8);
            }
            int rb = br + it * 16;
            cp_async16(sb + OFF_BH + (uint32_t)(rb * 272 + bq * 16),
                       Bp + (size_t)rb * N + bq * 8);
        }
    };

    float acc[2][8][4];
    #pragma unroll
    for (int i = 0; i < 2; i++)
        #pragma unroll
        for (int j = 0; j < 8; j++)
            #pragma unroll
            for (int t = 0; t < 4; t++) acc[i][j][t] = 0.f;

    const int nch = K >> 5;

    issue(0, 0); cp_commit();
    issue(1, 1); cp_commit();

    const int lrow16 = lane & 15;
    const int khalf  = (lane >> 4) * 8;
    const uint32_t l7 = lane & 7, mh = (lane >> 3) & 1, kh = (lane >> 4) & 1;

    for (int c = 0; c < nch; c++) {
        cp_wait<1>();
        __syncthreads();
        if (c + 2 < nch) issue(c + 2, (c + 2) % NSTAGE);
        cp_commit();

        const uint32_t bb = smb + (c % NSTAGE) * STAGE_SZ;
        #pragma unroll
        for (int s = 0; s < 2; s++) {
            const int ks = s * 16;
            // B fragments: 4 x4-trans loads cover 8 n8-tiles
            uint32_t bh[4][4];
            const uint32_t brow = (uint32_t)((ks + mh * 8 + l7) * 272);
            #pragma unroll
            for (int nj = 0; nj < 4; nj++)
                ldsm_x4_t(bh[nj], bb + OFF_BH + brow +
                          (uint32_t)((wn + nj * 16 + kh * 8) * 2));
            #pragma unroll
            for (int mi = 0; mi < 2; mi++) {
                uint32_t ah[4], al[4];
                const uint32_t aoff =
                    (uint32_t)((wm + mi * 16 + lrow16) * 80 + (ks + khalf) * 2);
                ldsm_x4(ah, bb + OFF_AH + aoff);
                if (TWOPASS) ldsm_x4(al, bb + OFF_AL + aoff);
                #pragma unroll
                for (int nj = 0; nj < 4; nj++) {
                    mma16816(acc[mi][nj * 2],     ah, bh[nj]);
                    mma16816(acc[mi][nj * 2 + 1], ah, bh[nj] + 2);
                    if (TWOPASS) {
                        mma16816(acc[mi][nj * 2],     al, bh[nj]);
                        mma16816(acc[mi][nj * 2 + 1], al, bh[nj] + 2);
                    }
                }
            }
        }
    }

    const int r_in = lane >> 2;
    const int c_in = (lane & 3) * 2;
    __half* Chb = HILO ? (Ch + (size_t)bz * M * N) : nullptr;
    __half* Clb = HILO ? (Cl + (size_t)bz * M * N) : nullptr;
    float*  Cb  = HILO ? nullptr : (C + (size_t)bz * M * N);

    #pragma unroll
    for (int mi = 0; mi < 2; mi++) {
        const int r0 = m0 + wm + mi * 16 + r_in;
        const float b0 = bias[r0];
        const float b1 = bias[r0 + 8];
        #pragma unroll
        for (int ni = 0; ni < 8; ni++) {
            const int col = n0 + wn + ni * 8 + c_in;
            float v0 = acc[mi][ni][0] + b0, v1 = acc[mi][ni][1] + b0;
            float v2 = acc[mi][ni][2] + b1, v3 = acc[mi][ni][3] + b1;
            if (HILO) {
                __half h0 = __float2half_rn(v0), h1 = __float2half_rn(v1);
                __half h2 = __float2half_rn(v2), h3 = __float2half_rn(v3);
                __half l0 = __float2half_rn(__fsub_rn(v0, __half2float(h0)));
                __half l1 = __float2half_rn(__fsub_rn(v1, __half2float(h1)));
                __half l2 = __float2half_rn(__fsub_rn(v2, __half2float(h2)));
                __half l3 = __float2half_rn(__fsub_rn(v3, __half2float(h3)));
                *(__half2*)(Chb + (size_t)r0 * N + col)       = __halves2half2(h0, h1);
                *(__half2*)(Clb + (size_t)r0 * N + col)       = __halves2half2(l0, l1);
                *(__half2*)(Chb + (size_t)(r0 + 8) * N + col) = __halves2half2(h2, h3);
                *(__half2*)(Clb + (size_t)(r0 + 8) * N + col) = __halves2half2(l2, l3);
            } else {
                float m0f = cmask[(size_t)bz * N + col];
                float m1f = cmask[(size_t)bz * N + col + 1];
                *(float2*)(Cb + (size_t)r0 * N + col)       = make_float2(v0 * m0f, v1 * m1f);
                *(float2*)(Cb + (size_t)(r0 + 8) * N + col) = make_float2(v2 * m0f, v3 * m1f);
            }
        }
    }
}

// ============================================================================
// Tensor-core windowed attention: one CTA per (window, head, batch).
// QK^T (3-pass hi/lo) -> warp-local softmax -> P hi/lo -> AV (3-pass) ->
// /sum, exact GELU, write g_Bo fp16.  (unchanged from R7 — measured good)
// ============================================================================
#define AT_QH  0
#define AT_QL  17408
#define AT_KH  34816
#define AT_KL  52224
#define AT_VH  69632
#define AT_VL  87040
#define AT_PH  0        // overlays QH+QL after QK phase
#define AT_PL  34816    // overlays KH+KL
#define AT_SUM 104448   // float[128]
#define AT_MSK 104960   // float[128]
#define AT_SMEM 105472

__global__ __launch_bounds__(256, 2) void attn_mma(const float* __restrict__ masks)
{
    extern __shared__ char sm[];
    const uint32_t smb = smem_u32(sm);
    const int tid = threadIdx.x, warp = tid >> 5, lane = tid & 31;
    const int wh = blockIdx.x, w = wh >> 3, h = wh & 7, b = blockIdx.y;
    const size_t base = ((size_t)b * DKK + h * 64) * SS + (size_t)w * WW;

    {
        const __half* srcs[6] = { g_Qh + base, g_Ql + base, g_Kh + base,
                                  g_Kl + base, g_Vh + base, g_Vl + base };
        #pragma unroll
        for (int t = 0; t < 6; t++) {
            const uint32_t dstb = smb + t * 17408;
            #pragma unroll
            for (int it = 0; it < 4; it++) {
                int idx = tid + it * 256;
                int row = idx >> 4, ch = idx & 15;
                cp_async16(dstb + row * 272 + ch * 16,
                           srcs[t] + (size_t)row * SS + ch * 8);
            }
        }
        cp_commit();
    }
    if (tid < 32) {
        float4 mv = *(const float4*)(masks + (size_t)b * SS + w * WW + tid * 4);
        *(float4*)(sm + AT_MSK + tid * 16) = mv;
    }
    cp_wait<0>();
    __syncthreads();

    const int r_in = lane >> 2, c_in = (lane & 3) * 2;
    const uint32_t l7 = lane & 7, mh = (lane >> 3) & 1, kh = (lane >> 4) & 1;
    const int i0w = warp * 16;

    float acc[16][4];
    #pragma unroll
    for (int f = 0; f < 16; f++)
        #pragma unroll
        for (int t = 0; t < 4; t++) acc[f][t] = 0.f;

    #pragma unroll
    for (int s = 0; s < 4; s++) {
        uint32_t ah[4], al[4];
        const uint32_t aaddr = smb + (s * 16 + kh * 8 + l7) * 272 + (i0w + mh * 8) * 2;
        ldsm_x4_t(ah, aaddr + AT_QH);
        ldsm_x4_t(al, aaddr + AT_QL);
        #pragma unroll
        for (int q = 0; q < 8; q++) {
            const uint32_t baddr = smb + AT_KH +
                (s * 16 + mh * 8 + l7) * 272 + (q * 16 + kh * 8) * 2;
            uint32_t bh4[4], bl4[4];
            ldsm_x4_t(bh4, baddr);
            ldsm_x4_t(bl4, baddr + (AT_KL - AT_KH));
            const int f0 = q * 2;
            mma16816(acc[f0],     ah, bh4);
            mma16816(acc[f0],     al, bh4);
            mma16816(acc[f0],     ah, bl4);
            mma16816(acc[f0 + 1], ah, bh4 + 2);
            mma16816(acc[f0 + 1], al, bh4 + 2);
            mma16816(acc[f0 + 1], ah, bl4 + 2);
        }
    }

    const float* mk = (const float*)(sm + AT_MSK);
    float mx0 = -1e30f, mx1 = -1e30f;
    #pragma unroll
    for (int f = 0; f < 16; f++) {
        const int j = f * 8 + c_in;
        const float mj0 = mk[j], mj1 = mk[j + 1];
        acc[f][0] = (mj0 > 0.f) ? acc[f][0] * 0.125f : -1e9f;
        acc[f][1] = (mj1 > 0.f) ? acc[f][1] * 0.125f : -1e9f;
        acc[f][2] = (mj0 > 0.f) ? acc[f][2] * 0.125f : -1e9f;
        acc[f][3] = (mj1 > 0.f) ? acc[f][3] * 0.125f : -1e9f;
        mx0 = fmaxf(mx0, fmaxf(acc[f][0], acc[f][1]));
        mx1 = fmaxf(mx1, fmaxf(acc[f][2], acc[f][3]));
    }
    mx0 = fmaxf(mx0, __shfl_xor_sync(0xffffffffu, mx0, 1));
    mx0 = fmaxf(mx0, __shfl_xor_sync(0xffffffffu, mx0, 2));
    mx1 = fmaxf(mx1, __shfl_xor_sync(0xffffffffu, mx1, 1));
    mx1 = fmaxf(mx1, __shfl_xor_sync(0xffffffffu, mx1, 2));

    float s0 = 0.f, s1 = 0.f;
    #pragma unroll
    for (int f = 0; f < 16; f++) {
        acc[f][0] = __expf(acc[f][0] - mx0);
        acc[f][1] = __expf(acc[f][1] - mx0);
        acc[f][2] = __expf(acc[f][2] - mx1);
        acc[f][3] = __expf(acc[f][3] - mx1);
        s0 += acc[f][0] + acc[f][1];
        s1 += acc[f][2] + acc[f][3];
    }
    s0 += __shfl_xor_sync(0xffffffffu, s0, 1);
    s0 += __shfl_xor_sync(0xffffffffu, s0, 2);
    s1 += __shfl_xor_sync(0xffffffffu, s1, 1);
    s1 += __shfl_xor_sync(0xffffffffu, s1, 2);
    if ((lane & 3) == 0) {
        ((float*)(sm + AT_SUM))[i0w + r_in]     = s0;
        ((float*)(sm + AT_SUM))[i0w + r_in + 8] = s1;
    }

    __syncthreads();

    #pragma unroll
    for (int f = 0; f < 16; f++) {
        const int j = f * 8 + c_in;
        const int i = i0w + r_in;
        #pragma unroll
        for (int t = 0; t < 4; t++) {
            const int jj = j + (t & 1);
            const int ii = i + (t >> 1) * 8;
            const float p = acc[f][t];
            const __half ph = __float2half_rn(p);
            const __half pl = __float2half_rn(__fsub_rn(p, __half2float(ph)));
            *(__half*)(sm + AT_PH + (jj * 136 + ii) * 2) = ph;
            *(__half*)(sm + AT_PL + (jj * 136 + ii) * 2) = pl;
        }
    }
    __syncthreads();

    const int wam = (warp >> 2) * 32, wan = (warp & 3) * 32;
    float oc[2][4][4];
    #pragma unroll
    for (int mi = 0; mi < 2; mi++)
        #pragma unroll
        for (int ni = 0; ni < 4; ni++)
            #pragma unroll
            for (int t = 0; t < 4; t++) oc[mi][ni][t] = 0.f;

    #pragma unroll
    for (int s = 0; s < 8; s++) {
        uint32_t avh[2][4], avl[2][4];
        #pragma unroll
        for (int mi = 0; mi < 2; mi++) {
            const uint32_t aaddr = smb + AT_VH +
                (wam + mi * 16 + (lane & 15)) * 272 + (s * 16 + (lane >> 4) * 8) * 2;
            ldsm_x4(avh[mi], aaddr);
            ldsm_x4(avl[mi], aaddr + (AT_VL - AT_VH));
        }
        #pragma unroll
        for (int q = 0; q < 2; q++) {
            const uint32_t baddr = smb + AT_PH +
                (s * 16 + mh * 8 + l7) * 272 + (wan + q * 16 + kh * 8) * 2;
            uint32_t bph[4], bpl[4];
            ldsm_x4_t(bph, baddr);
            ldsm_x4_t(bpl, baddr + (AT_PL - AT_PH));
            #pragma unroll
            for (int mi = 0; mi < 2; mi++) {
                const int n0f = q * 2;
                mma16816(oc[mi][n0f],     avh[mi], bph);
                mma16816(oc[mi][n0f],     avl[mi], bph);
                mma16816(oc[mi][n0f],     avh[mi], bpl);
                mma16816(oc[mi][n0f + 1], avh[mi], bph + 2);
                mma16816(oc[mi][n0f + 1], avl[mi], bph + 2);
                mma16816(oc[mi][n0f + 1], avh[mi], bpl + 2);
            }
        }
    }

    const float* sums = (const float*)(sm + AT_SUM);
    #pragma unroll
    for (int mi = 0; mi < 2; mi++) {
        const int d = wam + mi * 16 + r_in;
        #pragma unroll
        for (int ni = 0; ni < 4; ni++) {
            const int i = wan + ni * 8 + c_in;
            const float inv0 = 1.f / sums[i];
            const float inv1 = 1.f / sums[i + 1];
            const float o0 = gelu_exact(oc[mi][ni][0] * inv0);
            const float o1 = gelu_exact(oc[mi][ni][1] * inv1);
            const float o2 = gelu_exact(oc[mi][ni][2] * inv0);
            const float o3 = gelu_exact(oc[mi][ni][3] * inv1);
            const size_t g = base + (size_t)d * SS + i;
            *(__half2*)(g_Bo + g)          = __halves2half2(__float2half_rn(o0), __float2half_rn(o1));
            *(__half2*)(g_Bo + g + 8 * SS) = __halves2half2(__float2half_rn(o2), __float2half_rn(o3));
        }
    }
}

// ---------------------------------------------------------------------------
extern "C" void kernel_launch(void* const* d_in, const int* in_sizes, int n_in,
                              void* d_out, int out_size)
{
    const float* qk    = (const float*)d_in[0];
    const float* v     = (const float*)d_in[1];
    const float* masks = (const float*)d_in[2];
    const float* Wq    = (const float*)d_in[3];
    const float* bq    = (const float*)d_in[4];
    const float* Wk    = (const float*)d_in[5];
    const float* bk    = (const float*)d_in[6];
    const float* Wv    = (const float*)d_in[7];
    const float* bv    = (const float*)d_in[8];
    const float* Wo    = (const float*)d_in[9];
    const float* bo    = (const float*)d_in[10];
    float* out = (float*)d_out;

    __half *Bqk, *Bv, *Bo, *Qh, *Ql, *Kh, *Kl, *Vh, *Vl;
    __half *Wqh, *Wql, *Wkh, *Wkl, *Wvh, *Wvl, *Woh, *Wol;
    cudaGetSymbolAddress((void**)&Bqk, g_Bqk);
    cudaGetSymbolAddress((void**)&Bv,  g_Bv);
    cudaGetSymbolAddress((void**)&Bo,  g_Bo);
    cudaGetSymbolAddress((void**)&Qh, g_Qh); cudaGetSymbolAddress((void**)&Ql, g_Ql);
    cudaGetSymbolAddress((void**)&Kh, g_Kh); cudaGetSymbolAddress((void**)&Kl, g_Kl);
    cudaGetSymbolAddress((void**)&Vh, g_Vh); cudaGetSymbolAddress((void**)&Vl, g_Vl);
    cudaGetSymbolAddress((void**)&Wqh, g_Wqh); cudaGetSymbolAddress((void**)&Wql, g_Wql);
    cudaGetSymbolAddress((void**)&Wkh, g_Wkh); cudaGetSymbolAddress((void**)&Wkl, g_Wkl);
    cudaGetSymbolAddress((void**)&Wvh, g_Wvh); cudaGetSymbolAddress((void**)&Wvl, g_Wvl);
    cudaGetSymbolAddress((void**)&Woh, g_Woh); cudaGetSymbolAddress((void**)&Wol, g_Wol);

    cudaFuncSetAttribute((const void*)gemm_fp16<true, true>,
                         cudaFuncAttributeMaxDynamicSharedMemorySize, GSMEM_TOTAL);
    cudaFuncSetAttribute((const void*)gemm_fp16<false, false>,
                         cudaFuncAttributeMaxDynamicSharedMemorySize, GSMEM_TOTAL);
    cudaFuncSetAttribute(attn_mma,
                         cudaFuncAttributeMaxDynamicSharedMemorySize, AT_SMEM);

    dim3 blk(256);

    // ---- conversions ----
    const int nW = DKK * DD / 4;
    cvt_hilo<<<nW / 256, blk>>>((const float4*)Wq, (uint2*)Wqh, (uint2*)Wql, nW);
    cvt_hilo<<<nW / 256, blk>>>((const float4*)Wk, (uint2*)Wkh, (uint2*)Wkl, nW);
    cvt_hilo<<<nW / 256, blk>>>((const float4*)Wv, (uint2*)Wvh, (uint2*)Wvl, nW);
    cvt_hi  <<<nW / 256, blk>>>((const float4*)Wo, (uint2*)Woh, nW);
    const int nX = NB * DD * SS / 4;
    cvt_hi<<<nX / 256, blk>>>((const float4*)qk, (uint2*)Bqk, nX);
    cvt_hi<<<nX / 256, blk>>>((const float4*)v,  (uint2*)Bv,  nX);

    // ---- Q/K/V projections (2-pass A, write fp16 hi/lo) ----
    gemm_fp16<true, true><<<dim3(32, 4, NB), blk, GSMEM_TOTAL>>>(
        Wqh, Wql, Bqk, bq, nullptr, nullptr, Qh, Ql, DKK, SS, DD);
    gemm_fp16<true, true><<<dim3(32, 4, NB), blk, GSMEM_TOTAL>>>(
        Wkh, Wkl, Bqk, bk, nullptr, nullptr, Kh, Kl, DKK, SS, DD);
    gemm_fp16<true, true><<<dim3(32, 4, NB), blk, GSMEM_TOTAL>>>(
        Wvh, Wvl, Bv, bv, nullptr, nullptr, Vh, Vl, DKK, SS, DD);

    // ---- tensor-core attention + GELU (writes g_Bo fp16) ----
    attn_mma<<<dim3(NWIN * NH, NB), blk, AT_SMEM>>>(masks);

    // ---- output projection (single-pass A) + final mask (fp32 out) ----
    gemm_fp16<false, false><<<dim3(32, 8, NB), blk, GSMEM_TOTAL>>>(
        Woh, nullptr, Bo, bo, masks, out, nullptr, nullptr, DD, SS, DKK);
}

// round 10
// speedup vs baseline: 5.3018x; 1.4223x over previous
#include <cuda_runtime.h>
#include <cuda_fp16.h>
#include <math.h>
#include <stdint.h>

#define NB   8
#define SS   4096
#define DD   1024
#define DKK  512
#define NH   8
#define WW   128
#define DH   64
#define NWIN 32   // S / W

// fp16 operand buffers (device globals: allowed)
__device__ __half g_Bqk[(size_t)NB * DD * SS];    // qk -> fp16 (GEMM B operand)
__device__ __half g_Bv [(size_t)NB * DD * SS];    // v  -> fp16
__device__ __half g_Bo [(size_t)NB * DKK * SS];   // GELU(attn out) fp16 (written by attn)
__device__ __half g_Qh[(size_t)NB * DKK * SS], g_Ql[(size_t)NB * DKK * SS];
__device__ __half g_Kh[(size_t)NB * DKK * SS], g_Kl[(size_t)NB * DKK * SS];
__device__ __half g_Vh[(size_t)NB * DKK * SS], g_Vl[(size_t)NB * DKK * SS];
__device__ __half g_Wqh[DKK * DD];
__device__ __half g_Wkh[DKK * DD];
__device__ __half g_Wvh[DKK * DD];
__device__ __half g_Woh[DD * DKK];

// ============================================================================
// PTX helpers (sm_80+ only — compute_103-safe)
// ============================================================================
__device__ __forceinline__ uint32_t smem_u32(const void* p) {
    uint32_t a;
    asm("{ .reg .u64 t; cvta.to.shared.u64 t, %1; cvt.u32.u64 %0, t; }"
        : "=r"(a) : "l"(p));
    return a;
}
__device__ __forceinline__ void ldsm_x4(uint32_t* r, uint32_t addr) {
    asm volatile("ldmatrix.sync.aligned.m8n8.x4.shared.b16 {%0,%1,%2,%3}, [%4];"
                 : "=r"(r[0]), "=r"(r[1]), "=r"(r[2]), "=r"(r[3]) : "r"(addr));
}
__device__ __forceinline__ void ldsm_x4_t(uint32_t* r, uint32_t addr) {
    asm volatile("ldmatrix.sync.aligned.m8n8.x4.trans.shared.b16 {%0,%1,%2,%3}, [%4];"
                 : "=r"(r[0]), "=r"(r[1]), "=r"(r[2]), "=r"(r[3]) : "r"(addr));
}
__device__ __forceinline__ void mma16816(float* d, const uint32_t* a, const uint32_t* b) {
    asm volatile(
        "mma.sync.aligned.m16n8k16.row.col.f32.f16.f16.f32 "
        "{%0,%1,%2,%3},{%4,%5,%6,%7},{%8,%9},{%0,%1,%2,%3};"
        : "+f"(d[0]), "+f"(d[1]), "+f"(d[2]), "+f"(d[3])
        : "r"(a[0]), "r"(a[1]), "r"(a[2]), "r"(a[3]), "r"(b[0]), "r"(b[1]));
}
__device__ __forceinline__ void cp_async16(uint32_t dst, const void* src) {
    asm volatile("cp.async.cg.shared.global [%0], [%1], 16;" :: "r"(dst), "l"(src));
}
__device__ __forceinline__ void cp_commit() {
    asm volatile("cp.async.commit_group;" ::: "memory");
}
template<int N> __device__ __forceinline__ void cp_wait() {
    asm volatile("cp.async.wait_group %0;" :: "n"(N) : "memory");
}
__device__ __forceinline__ float gelu_exact(float x) { return x * normcdff(x); }

// ============================================================================
// Conversion kernels
// ============================================================================
__global__ void cvt_hi(const float4* __restrict__ src, uint2* __restrict__ hi, int n4)
{
    int i = blockIdx.x * blockDim.x + threadIdx.x;
    if (i >= n4) return;
    float4 v = src[i];
    unsigned h0 = __half_as_ushort(__float2half_rn(v.x));
    unsigned h1 = __half_as_ushort(__float2half_rn(v.y));
    unsigned h2 = __half_as_ushort(__float2half_rn(v.z));
    unsigned h3 = __half_as_ushort(__float2half_rn(v.w));
    hi[i] = make_uint2(h0 | (h1 << 16), h2 | (h3 << 16));
}

// ============================================================================
// fp16 GEMM via mma.sync + cp.async:  C[bz] = A @ B[bz] + bias
// Single-pass fp16 A (weights). Accumulate fp32.
// HILO=true : write hi/lo fp16 outputs (QKV projections, no mask)
// HILO=false: write fp32 output with column mask (final projection)
// CTA 128x128, warp grid 4(m) x 2(n), warp tile 32x64, K-chunk 32, 3 stages.
// A smem [m][k] pitch 80B, B smem [k][n] pitch 272B — conflict-free ldmatrix.
// ============================================================================
#define OFF_AH   0
#define OFF_BH   10240
#define STAGE_SZ 18944
#define NSTAGE   3
#define GSMEM_TOTAL (NSTAGE * STAGE_SZ)

template<bool HILO>
__global__ __launch_bounds__(256, 2) void gemm_fp16(
    const __half* __restrict__ Ah,
    const __half* __restrict__ Bg,
    const float* __restrict__ bias,
    const float* __restrict__ cmask,
    float* __restrict__ C,
    __half* __restrict__ Ch,
    __half* __restrict__ Cl,
    int M, int N, int K)
{
    extern __shared__ char sm[];
    const int tid  = threadIdx.x;
    const int warp = tid >> 5;
    const int lane = tid & 31;
    const int bx = blockIdx.x, by = blockIdx.y, bz = blockIdx.z;
    const int n0 = bx * 128, m0 = by * 128;
    const int wm = (warp >> 1) * 32;     // 4 m-groups of 32
    const int wn = (warp & 1) * 64;      // 2 n-groups of 64

    const __half* Bb = Bg + (size_t)bz * K * N;
    const uint32_t smb = smem_u32(sm);

    const int ar = tid >> 2, aq = tid & 3;
    const int br = tid >> 4, bq = tid & 15;

    auto issue = [&](int c, int st) {
        const uint32_t sb = smb + st * STAGE_SZ;
        const __half* Ahp = Ah + (size_t)m0 * K + c * 32;
        const __half* Bp  = Bb + (size_t)(c * 32) * N + n0;
        #pragma unroll
        for (int it = 0; it < 2; it++) {
            int r = ar + it * 64;
            cp_async16(sb + OFF_AH + (uint32_t)(r * 80 + aq * 16),
                       Ahp + (size_t)r * K + aq * 8);
            int rb = br + it * 16;
            cp_async16(sb + OFF_BH + (uint32_t)(rb * 272 + bq * 16),
                       Bp + (size_t)rb * N + bq * 8);
        }
    };

    float acc[2][8][4];
    #pragma unroll
    for (int i = 0; i < 2; i++)
        #pragma unroll
        for (int j = 0; j < 8; j++)
            #pragma unroll
            for (int t = 0; t < 4; t++) acc[i][j][t] = 0.f;

    const int nch = K >> 5;

    issue(0, 0); cp_commit();
    issue(1, 1); cp_commit();

    const int lrow16 = lane & 15;
    const int khalf  = (lane >> 4) * 8;
    const uint32_t l7 = lane & 7, mh = (lane >> 3) & 1, kh = (lane >> 4) & 1;

    for (int c = 0; c < nch; c++) {
        cp_wait<1>();
        __syncthreads();
        if (c + 2 < nch) issue(c + 2, (c + 2) % NSTAGE);
        cp_commit();

        const uint32_t bb = smb + (c % NSTAGE) * STAGE_SZ;
        #pragma unroll
        for (int s = 0; s < 2; s++) {
            const int ks = s * 16;
            // B fragments: 4 x4-trans loads cover 8 n8-tiles
            uint32_t bh[4][4];
            const uint32_t brow = (uint32_t)((ks + mh * 8 + l7) * 272);
            #pragma unroll
            for (int nj = 0; nj < 4; nj++)
                ldsm_x4_t(bh[nj], bb + OFF_BH + brow +
                          (uint32_t)((wn + nj * 16 + kh * 8) * 2));
            #pragma unroll
            for (int mi = 0; mi < 2; mi++) {
                uint32_t ah[4];
                const uint32_t aoff =
                    (uint32_t)((wm + mi * 16 + lrow16) * 80 + (ks + khalf) * 2);
                ldsm_x4(ah, bb + OFF_AH + aoff);
                #pragma unroll
                for (int nj = 0; nj < 4; nj++) {
                    mma16816(acc[mi][nj * 2],     ah, bh[nj]);
                    mma16816(acc[mi][nj * 2 + 1], ah, bh[nj] + 2);
                }
            }
        }
    }

    const int r_in = lane >> 2;
    const int c_in = (lane & 3) * 2;
    __half* Chb = HILO ? (Ch + (size_t)bz * M * N) : nullptr;
    __half* Clb = HILO ? (Cl + (size_t)bz * M * N) : nullptr;
    float*  Cb  = HILO ? nullptr : (C + (size_t)bz * M * N);

    #pragma unroll
    for (int mi = 0; mi < 2; mi++) {
        const int r0 = m0 + wm + mi * 16 + r_in;
        const float b0 = bias[r0];
        const float b1 = bias[r0 + 8];
        #pragma unroll
        for (int ni = 0; ni < 8; ni++) {
            const int col = n0 + wn + ni * 8 + c_in;
            float v0 = acc[mi][ni][0] + b0, v1 = acc[mi][ni][1] + b0;
            float v2 = acc[mi][ni][2] + b1, v3 = acc[mi][ni][3] + b1;
            if (HILO) {
                __half h0 = __float2half_rn(v0), h1 = __float2half_rn(v1);
                __half h2 = __float2half_rn(v2), h3 = __float2half_rn(v3);
                __half l0 = __float2half_rn(__fsub_rn(v0, __half2float(h0)));
                __half l1 = __float2half_rn(__fsub_rn(v1, __half2float(h1)));
                __half l2 = __float2half_rn(__fsub_rn(v2, __half2float(h2)));
                __half l3 = __float2half_rn(__fsub_rn(v3, __half2float(h3)));
                *(__half2*)(Chb + (size_t)r0 * N + col)       = __halves2half2(h0, h1);
                *(__half2*)(Clb + (size_t)r0 * N + col)       = __halves2half2(l0, l1);
                *(__half2*)(Chb + (size_t)(r0 + 8) * N + col) = __halves2half2(h2, h3);
                *(__half2*)(Clb + (size_t)(r0 + 8) * N + col) = __halves2half2(l2, l3);
            } else {
                float m0f = cmask[(size_t)bz * N + col];
                float m1f = cmask[(size_t)bz * N + col + 1];
                *(float2*)(Cb + (size_t)r0 * N + col)       = make_float2(v0 * m0f, v1 * m1f);
                *(float2*)(Cb + (size_t)(r0 + 8) * N + col) = make_float2(v2 * m0f, v3 * m1f);
            }
        }
    }
}

// ============================================================================
// Tensor-core windowed attention: one CTA per (window, head, batch).
// QK^T (3-pass hi/lo) -> warp-local softmax -> P hi/lo -> AV (3-pass) ->
// /sum, exact GELU, write g_Bo fp16.  (unchanged — measured good)
// ============================================================================
#define AT_QH  0
#define AT_QL  17408
#define AT_KH  34816
#define AT_KL  52224
#define AT_VH  69632
#define AT_VL  87040
#define AT_PH  0        // overlays QH+QL after QK phase
#define AT_PL  34816    // overlays KH+KL
#define AT_SUM 104448   // float[128]
#define AT_MSK 104960   // float[128]
#define AT_SMEM 105472

__global__ __launch_bounds__(256, 2) void attn_mma(const float* __restrict__ masks)
{
    extern __shared__ char sm[];
    const uint32_t smb = smem_u32(sm);
    const int tid = threadIdx.x, warp = tid >> 5, lane = tid & 31;
    const int wh = blockIdx.x, w = wh >> 3, h = wh & 7, b = blockIdx.y;
    const size_t base = ((size_t)b * DKK + h * 64) * SS + (size_t)w * WW;

    {
        const __half* srcs[6] = { g_Qh + base, g_Ql + base, g_Kh + base,
                                  g_Kl + base, g_Vh + base, g_Vl + base };
        #pragma unroll
        for (int t = 0; t < 6; t++) {
            const uint32_t dstb = smb + t * 17408;
            #pragma unroll
            for (int it = 0; it < 4; it++) {
                int idx = tid + it * 256;
                int row = idx >> 4, ch = idx & 15;
                cp_async16(dstb + row * 272 + ch * 16,
                           srcs[t] + (size_t)row * SS + ch * 8);
            }
        }
        cp_commit();
    }
    if (tid < 32) {
        float4 mv = *(const float4*)(masks + (size_t)b * SS + w * WW + tid * 4);
        *(float4*)(sm + AT_MSK + tid * 16) = mv;
    }
    cp_wait<0>();
    __syncthreads();

    const int r_in = lane >> 2, c_in = (lane & 3) * 2;
    const uint32_t l7 = lane & 7, mh = (lane >> 3) & 1, kh = (lane >> 4) & 1;
    const int i0w = warp * 16;

    float acc[16][4];
    #pragma unroll
    for (int f = 0; f < 16; f++)
        #pragma unroll
        for (int t = 0; t < 4; t++) acc[f][t] = 0.f;

    #pragma unroll
    for (int s = 0; s < 4; s++) {
        uint32_t ah[4], al[4];
        const uint32_t aaddr = smb + (s * 16 + kh * 8 + l7) * 272 + (i0w + mh * 8) * 2;
        ldsm_x4_t(ah, aaddr + AT_QH);
        ldsm_x4_t(al, aaddr + AT_QL);
        #pragma unroll
        for (int q = 0; q < 8; q++) {
            const uint32_t baddr = smb + AT_KH +
                (s * 16 + mh * 8 + l7) * 272 + (q * 16 + kh * 8) * 2;
            uint32_t bh4[4], bl4[4];
            ldsm_x4_t(bh4, baddr);
            ldsm_x4_t(bl4, baddr + (AT_KL - AT_KH));
            const int f0 = q * 2;
            mma16816(acc[f0],     ah, bh4);
            mma16816(acc[f0],     al, bh4);
            mma16816(acc[f0],     ah, bl4);
            mma16816(acc[f0 + 1], ah, bh4 + 2);
            mma16816(acc[f0 + 1], al, bh4 + 2);
            mma16816(acc[f0 + 1], ah, bl4 + 2);
        }
    }

    const float* mk = (const float*)(sm + AT_MSK);
    float mx0 = -1e30f, mx1 = -1e30f;
    #pragma unroll
    for (int f = 0; f < 16; f++) {
        const int j = f * 8 + c_in;
        const float mj0 = mk[j], mj1 = mk[j + 1];
        acc[f][0] = (mj0 > 0.f) ? acc[f][0] * 0.125f : -1e9f;
        acc[f][1] = (mj1 > 0.f) ? acc[f][1] * 0.125f : -1e9f;
        acc[f][2] = (mj0 > 0.f) ? acc[f][2] * 0.125f : -1e9f;
        acc[f][3] = (mj1 > 0.f) ? acc[f][3] * 0.125f : -1e9f;
        mx0 = fmaxf(mx0, fmaxf(acc[f][0], acc[f][1]));
        mx1 = fmaxf(mx1, fmaxf(acc[f][2], acc[f][3]));
    }
    mx0 = fmaxf(mx0, __shfl_xor_sync(0xffffffffu, mx0, 1));
    mx0 = fmaxf(mx0, __shfl_xor_sync(0xffffffffu, mx0, 2));
    mx1 = fmaxf(mx1, __shfl_xor_sync(0xffffffffu, mx1, 1));
    mx1 = fmaxf(mx1, __shfl_xor_sync(0xffffffffu, mx1, 2));

    float s0 = 0.f, s1 = 0.f;
    #pragma unroll
    for (int f = 0; f < 16; f++) {
        acc[f][0] = __expf(acc[f][0] - mx0);
        acc[f][1] = __expf(acc[f][1] - mx0);
        acc[f][2] = __expf(acc[f][2] - mx1);
        acc[f][3] = __expf(acc[f][3] - mx1);
        s0 += acc[f][0] + acc[f][1];
        s1 += acc[f][2] + acc[f][3];
    }
    s0 += __shfl_xor_sync(0xffffffffu, s0, 1);
    s0 += __shfl_xor_sync(0xffffffffu, s0, 2);
    s1 += __shfl_xor_sync(0xffffffffu, s1, 1);
    s1 += __shfl_xor_sync(0xffffffffu, s1, 2);
    if ((lane & 3) == 0) {
        ((float*)(sm + AT_SUM))[i0w + r_in]     = s0;
        ((float*)(sm + AT_SUM))[i0w + r_in + 8] = s1;
    }

    __syncthreads();

    #pragma unroll
    for (int f = 0; f < 16; f++) {
        const int j = f * 8 + c_in;
        const int i = i0w + r_in;
        #pragma unroll
        for (int t = 0; t < 4; t++) {
            const int jj = j + (t & 1);
            const int ii = i + (t >> 1) * 8;
            const float p = acc[f][t];
            const __half ph = __float2half_rn(p);
            const __half pl = __float2half_rn(__fsub_rn(p, __half2float(ph)));
            *(__half*)(sm + AT_PH + (jj * 136 + ii) * 2) = ph;
            *(__half*)(sm + AT_PL + (jj * 136 + ii) * 2) = pl;
        }
    }
    __syncthreads();

    const int wam = (warp >> 2) * 32, wan = (warp & 3) * 32;
    float oc[2][4][4];
    #pragma unroll
    for (int mi = 0; mi < 2; mi++)
        #pragma unroll
        for (int ni = 0; ni < 4; ni++)
            #pragma unroll
            for (int t = 0; t < 4; t++) oc[mi][ni][t] = 0.f;

    #pragma unroll
    for (int s = 0; s < 8; s++) {
        uint32_t avh[2][4], avl[2][4];
        #pragma unroll
        for (int mi = 0; mi < 2; mi++) {
            const uint32_t aaddr = smb + AT_VH +
                (wam + mi * 16 + (lane & 15)) * 272 + (s * 16 + (lane >> 4) * 8) * 2;
            ldsm_x4(avh[mi], aaddr);
            ldsm_x4(avl[mi], aaddr + (AT_VL - AT_VH));
        }
        #pragma unroll
        for (int q = 0; q < 2; q++) {
            const uint32_t baddr = smb + AT_PH +
                (s * 16 + mh * 8 + l7) * 272 + (wan + q * 16 + kh * 8) * 2;
            uint32_t bph[4], bpl[4];
            ldsm_x4_t(bph, baddr);
            ldsm_x4_t(bpl, baddr + (AT_PL - AT_PH));
            #pragma unroll
            for (int mi = 0; mi < 2; mi++) {
                const int n0f = q * 2;
                mma16816(oc[mi][n0f],     avh[mi], bph);
                mma16816(oc[mi][n0f],     avl[mi], bph);
                mma16816(oc[mi][n0f],     avh[mi], bpl);
                mma16816(oc[mi][n0f + 1], avh[mi], bph + 2);
                mma16816(oc[mi][n0f + 1], avl[mi], bph + 2);
                mma16816(oc[mi][n0f + 1], avh[mi], bpl + 2);
            }
        }
    }

    const float* sums = (const float*)(sm + AT_SUM);
    #pragma unroll
    for (int mi = 0; mi < 2; mi++) {
        const int d = wam + mi * 16 + r_in;
        #pragma unroll
        for (int ni = 0; ni < 4; ni++) {
            const int i = wan + ni * 8 + c_in;
            const float inv0 = 1.f / sums[i];
            const float inv1 = 1.f / sums[i + 1];
            const float o0 = gelu_exact(oc[mi][ni][0] * inv0);
            const float o1 = gelu_exact(oc[mi][ni][1] * inv1);
            const float o2 = gelu_exact(oc[mi][ni][2] * inv0);
            const float o3 = gelu_exact(oc[mi][ni][3] * inv1);
            const size_t g = base + (size_t)d * SS + i;
            *(__half2*)(g_Bo + g)          = __halves2half2(__float2half_rn(o0), __float2half_rn(o1));
            *(__half2*)(g_Bo + g + 8 * SS) = __halves2half2(__float2half_rn(o2), __float2half_rn(o3));
        }
    }
}

// ---------------------------------------------------------------------------
extern "C" void kernel_launch(void* const* d_in, const int* in_sizes, int n_in,
                              void* d_out, int out_size)
{
    const float* qk    = (const float*)d_in[0];
    const float* v     = (const float*)d_in[1];
    const float* masks = (const float*)d_in[2];
    const float* Wq    = (const float*)d_in[3];
    const float* bq    = (const float*)d_in[4];
    const float* Wk    = (const float*)d_in[5];
    const float* bk    = (const float*)d_in[6];
    const float* Wv    = (const float*)d_in[7];
    const float* bv    = (const float*)d_in[8];
    const float* Wo    = (const float*)d_in[9];
    const float* bo    = (const float*)d_in[10];
    float* out = (float*)d_out;

    __half *Bqk, *Bv, *Bo, *Qh, *Ql, *Kh, *Kl, *Vh, *Vl;
    __half *Wqh, *Wkh, *Wvh, *Woh;
    cudaGetSymbolAddress((void**)&Bqk, g_Bqk);
    cudaGetSymbolAddress((void**)&Bv,  g_Bv);
    cudaGetSymbolAddress((void**)&Bo,  g_Bo);
    cudaGetSymbolAddress((void**)&Qh, g_Qh); cudaGetSymbolAddress((void**)&Ql, g_Ql);
    cudaGetSymbolAddress((void**)&Kh, g_Kh); cudaGetSymbolAddress((void**)&Kl, g_Kl);
    cudaGetSymbolAddress((void**)&Vh, g_Vh); cudaGetSymbolAddress((void**)&Vl, g_Vl);
    cudaGetSymbolAddress((void**)&Wqh, g_Wqh);
    cudaGetSymbolAddress((void**)&Wkh, g_Wkh);
    cudaGetSymbolAddress((void**)&Wvh, g_Wvh);
    cudaGetSymbolAddress((void**)&Woh, g_Woh);

    cudaFuncSetAttribute((const void*)gemm_fp16<true>,
                         cudaFuncAttributeMaxDynamicSharedMemorySize, GSMEM_TOTAL);
    cudaFuncSetAttribute((const void*)gemm_fp16<false>,
                         cudaFuncAttributeMaxDynamicSharedMemorySize, GSMEM_TOTAL);
    cudaFuncSetAttribute(attn_mma,
                         cudaFuncAttributeMaxDynamicSharedMemorySize, AT_SMEM);

    dim3 blk(256);

    // ---- conversions (weights single fp16 now) ----
    const int nW = DKK * DD / 4;
    cvt_hi<<<nW / 256, blk>>>((const float4*)Wq, (uint2*)Wqh, nW);
    cvt_hi<<<nW / 256, blk>>>((const float4*)Wk, (uint2*)Wkh, nW);
    cvt_hi<<<nW / 256, blk>>>((const float4*)Wv, (uint2*)Wvh, nW);
    cvt_hi<<<nW / 256, blk>>>((const float4*)Wo, (uint2*)Woh, nW);
    const int nX = NB * DD * SS / 4;
    cvt_hi<<<nX / 256, blk>>>((const float4*)qk, (uint2*)Bqk, nX);
    cvt_hi<<<nX / 256, blk>>>((const float4*)v,  (uint2*)Bv,  nX);

    // ---- Q/K/V projections (single-pass A, write fp16 hi/lo) ----
    gemm_fp16<true><<<dim3(32, 4, NB), blk, GSMEM_TOTAL>>>(
        Wqh, Bqk, bq, nullptr, nullptr, Qh, Ql, DKK, SS, DD);
    gemm_fp16<true><<<dim3(32, 4, NB), blk, GSMEM_TOTAL>>>(
        Wkh, Bqk, bk, nullptr, nullptr, Kh, Kl, DKK, SS, DD);
    gemm_fp16<true><<<dim3(32, 4, NB), blk, GSMEM_TOTAL>>>(
        Wvh, Bv, bv, nullptr, nullptr, Vh, Vl, DKK, SS, DD);

    // ---- tensor-core attention + GELU (writes g_Bo fp16) ----
    attn_mma<<<dim3(NWIN * NH, NB), blk, AT_SMEM>>>(masks);

    // ---- output projection (single-pass A) + final mask (fp32 out) ----
    gemm_fp16<false><<<dim3(32, 8, NB), blk, GSMEM_TOTAL>>>(
        Woh, Bo, bo, masks, out, nullptr, nullptr, DD, SS, DKK);
}

// round 12
// speedup vs baseline: 5.5694x; 1.0505x over previous
#include <cuda_runtime.h>
#include <cuda_fp16.h>
#include <math.h>
#include <stdint.h>

#define NB   8
#define SS   4096
#define DD   1024
#define DKK  512
#define NH   8
#define WW   128
#define DH   64
#define NWIN 32   // S / W

// fp16 operand buffers (device globals: allowed)
__device__ __half g_Bqk[(size_t)NB * DD * SS];
__device__ __half g_Bv [(size_t)NB * DD * SS];
__device__ __half g_Bo [(size_t)NB * DKK * SS];
__device__ __half g_Qh[(size_t)NB * DKK * SS], g_Ql[(size_t)NB * DKK * SS];
__device__ __half g_Kh[(size_t)NB * DKK * SS], g_Kl[(size_t)NB * DKK * SS];
__device__ __half g_Vh[(size_t)NB * DKK * SS], g_Vl[(size_t)NB * DKK * SS];
__device__ __half g_Wqh[DKK * DD];
__device__ __half g_Wkh[DKK * DD];
__device__ __half g_Wvh[DKK * DD];
__device__ __half g_Woh[DD * DKK];

// ============================================================================
// PTX helpers (sm_80+ only — compute_103-safe)
// ============================================================================
__device__ __forceinline__ uint32_t smem_u32(const void* p) {
    uint32_t a;
    asm("{ .reg .u64 t; cvta.to.shared.u64 t, %1; cvt.u32.u64 %0, t; }"
        : "=r"(a) : "l"(p));
    return a;
}
__device__ __forceinline__ void ldsm_x4(uint32_t* r, uint32_t addr) {
    asm volatile("ldmatrix.sync.aligned.m8n8.x4.shared.b16 {%0,%1,%2,%3}, [%4];"
                 : "=r"(r[0]), "=r"(r[1]), "=r"(r[2]), "=r"(r[3]) : "r"(addr));
}
__device__ __forceinline__ void ldsm_x4_t(uint32_t* r, uint32_t addr) {
    asm volatile("ldmatrix.sync.aligned.m8n8.x4.trans.shared.b16 {%0,%1,%2,%3}, [%4];"
                 : "=r"(r[0]), "=r"(r[1]), "=r"(r[2]), "=r"(r[3]) : "r"(addr));
}
__device__ __forceinline__ void mma16816(float* d, const uint32_t* a, const uint32_t* b) {
    asm volatile(
        "mma.sync.aligned.m16n8k16.row.col.f32.f16.f16.f32 "
        "{%0,%1,%2,%3},{%4,%5,%6,%7},{%8,%9},{%0,%1,%2,%3};"
        : "+f"(d[0]), "+f"(d[1]), "+f"(d[2]), "+f"(d[3])
        : "r"(a[0]), "r"(a[1]), "r"(a[2]), "r"(a[3]), "r"(b[0]), "r"(b[1]));
}
__device__ __forceinline__ void cp_async16(uint32_t dst, const void* src) {
    asm volatile("cp.async.cg.shared.global [%0], [%1], 16;" :: "r"(dst), "l"(src));
}
__device__ __forceinline__ void cp_commit() {
    asm volatile("cp.async.commit_group;" ::: "memory");
}
template<int N> __device__ __forceinline__ void cp_wait() {
    asm volatile("cp.async.wait_group %0;" :: "n"(N) : "memory");
}
__device__ __forceinline__ float gelu_exact(float x) { return x * normcdff(x); }

// ============================================================================
// Conversion kernels (merged)
// ============================================================================
__global__ void cvt_w4(const float4* __restrict__ s0, const float4* __restrict__ s1,
                       const float4* __restrict__ s2, const float4* __restrict__ s3,
                       uint2* __restrict__ d0, uint2* __restrict__ d1,
                       uint2* __restrict__ d2, uint2* __restrict__ d3)
{
    int i = blockIdx.x * blockDim.x + threadIdx.x;   // 4 * 131072 total
    int w = i >> 17, j = i & 131071;
    const float4* s = (w == 0) ? s0 : (w == 1) ? s1 : (w == 2) ? s2 : s3;
    uint2* d = (w == 0) ? d0 : (w == 1) ? d1 : (w == 2) ? d2 : d3;
    float4 v = s[j];
    unsigned h0 = __half_as_ushort(__float2half_rn(v.x));
    unsigned h1 = __half_as_ushort(__float2half_rn(v.y));
    unsigned h2 = __half_as_ushort(__float2half_rn(v.z));
    unsigned h3 = __half_as_ushort(__float2half_rn(v.w));
    d[j] = make_uint2(h0 | (h1 << 16), h2 | (h3 << 16));
}

__global__ void cvt_x2(const float4* __restrict__ s0, const float4* __restrict__ s1,
                       uint2* __restrict__ d0, uint2* __restrict__ d1, int n4)
{
    int i = blockIdx.x * blockDim.x + threadIdx.x;   // 2 * n4 total
    int w = (i >= n4), j = w ? (i - n4) : i;
    const float4* s = w ? s1 : s0;
    uint2* d = w ? d1 : d0;
    float4 v = s[j];
    unsigned h0 = __half_as_ushort(__float2half_rn(v.x));
    unsigned h1 = __half_as_ushort(__float2half_rn(v.y));
    unsigned h2 = __half_as_ushort(__float2half_rn(v.z));
    unsigned h3 = __half_as_ushort(__float2half_rn(v.w));
    d[j] = make_uint2(h0 | (h1 << 16), h2 | (h3 << 16));
}

// ============================================================================
// GEMM smem layout (shared by both GEMM kernels)
// ============================================================================
#define OFF_AH   0
#define OFF_BH   10240
#define STAGE_SZ 18944
#define NSTAGE   3
#define GSMEM_TOTAL (NSTAGE * STAGE_SZ)

// ============================================================================
// Merged QKV GEMM: grid (32, 12, NB). by>>2 selects Q/K/V segment.
// C = W @ B[bz] + bias, written as fp16 hi/lo.
// ============================================================================
__global__ __launch_bounds__(256, 2) void gemm_qkv(
    const float* __restrict__ bq, const float* __restrict__ bk,
    const float* __restrict__ bv)
{
    extern __shared__ char sm[];
    const int tid  = threadIdx.x;
    const int warp = tid >> 5;
    const int lane = tid & 31;
    const int bx = blockIdx.x, by = blockIdx.y, bz = blockIdx.z;
    const int seg = by >> 2, byy = by & 3;
    const int n0 = bx * 128, m0 = byy * 128;
    const int wm = (warp >> 1) * 32;
    const int wn = (warp & 1) * 64;
    const int M = DKK, N = SS, K = DD;

    const __half* Ah  = (seg == 0) ? g_Wqh : (seg == 1) ? g_Wkh : g_Wvh;
    const __half* Bgl = (seg == 2) ? g_Bv : g_Bqk;
    const float* bias = (seg == 0) ? bq : (seg == 1) ? bk : bv;
    __half* Ch = ((seg == 0) ? g_Qh : (seg == 1) ? g_Kh : g_Vh) + (size_t)bz * M * N;
    __half* Cl = ((seg == 0) ? g_Ql : (seg == 1) ? g_Kl : g_Vl) + (size_t)bz * M * N;

    const __half* Bb = Bgl + (size_t)bz * K * N;
    const uint32_t smb = smem_u32(sm);

    const int ar = tid >> 2, aq = tid & 3;
    const int br = tid >> 4, bq2 = tid & 15;

    auto issue = [&](int c, int st) {
        const uint32_t sb = smb + st * STAGE_SZ;
        const __half* Ahp = Ah + (size_t)m0 * K + c * 32;
        const __half* Bp  = Bb + (size_t)(c * 32) * N + n0;
        #pragma unroll
        for (int it = 0; it < 2; it++) {
            int r = ar + it * 64;
            cp_async16(sb + OFF_AH + (uint32_t)(r * 80 + aq * 16),
                       Ahp + (size_t)r * K + aq * 8);
            int rb = br + it * 16;
            cp_async16(sb + OFF_BH + (uint32_t)(rb * 272 + bq2 * 16),
                       Bp + (size_t)rb * N + bq2 * 8);
        }
    };

    float acc[2][8][4];
    #pragma unroll
    for (int i = 0; i < 2; i++)
        #pragma unroll
        for (int j = 0; j < 8; j++)
            #pragma unroll
            for (int t = 0; t < 4; t++) acc[i][j][t] = 0.f;

    const int nch = K >> 5;
    issue(0, 0); cp_commit();
    issue(1, 1); cp_commit();

    const int lrow16 = lane & 15;
    const int khalf  = (lane >> 4) * 8;
    const uint32_t l7 = lane & 7, mh = (lane >> 3) & 1, kh = (lane >> 4) & 1;

    for (int c = 0; c < nch; c++) {
        cp_wait<1>();
        __syncthreads();
        if (c + 2 < nch) issue(c + 2, (c + 2) % NSTAGE);
        cp_commit();

        const uint32_t bb = smb + (c % NSTAGE) * STAGE_SZ;
        #pragma unroll
        for (int s = 0; s < 2; s++) {
            const int ks = s * 16;
            uint32_t bh[4][4];
            const uint32_t brow = (uint32_t)((ks + mh * 8 + l7) * 272);
            #pragma unroll
            for (int nj = 0; nj < 4; nj++)
                ldsm_x4_t(bh[nj], bb + OFF_BH + brow +
                          (uint32_t)((wn + nj * 16 + kh * 8) * 2));
            #pragma unroll
            for (int mi = 0; mi < 2; mi++) {
                uint32_t ah[4];
                const uint32_t aoff =
                    (uint32_t)((wm + mi * 16 + lrow16) * 80 + (ks + khalf) * 2);
                ldsm_x4(ah, bb + OFF_AH + aoff);
                #pragma unroll
                for (int nj = 0; nj < 4; nj++) {
                    mma16816(acc[mi][nj * 2],     ah, bh[nj]);
                    mma16816(acc[mi][nj * 2 + 1], ah, bh[nj] + 2);
                }
            }
        }
    }

    const int r_in = lane >> 2;
    const int c_in = (lane & 3) * 2;
    #pragma unroll
    for (int mi = 0; mi < 2; mi++) {
        const int r0 = m0 + wm + mi * 16 + r_in;
        const float b0 = bias[r0];
        const float b1 = bias[r0 + 8];
        #pragma unroll
        for (int ni = 0; ni < 8; ni++) {
            const int col = n0 + wn + ni * 8 + c_in;
            float v0 = acc[mi][ni][0] + b0, v1 = acc[mi][ni][1] + b0;
            float v2 = acc[mi][ni][2] + b1, v3 = acc[mi][ni][3] + b1;
            __half h0 = __float2half_rn(v0), h1 = __float2half_rn(v1);
            __half h2 = __float2half_rn(v2), h3 = __float2half_rn(v3);
            __half l0 = __float2half_rn(__fsub_rn(v0, __half2float(h0)));
            __half l1 = __float2half_rn(__fsub_rn(v1, __half2float(h1)));
            __half l2 = __float2half_rn(__fsub_rn(v2, __half2float(h2)));
            __half l3 = __float2half_rn(__fsub_rn(v3, __half2float(h3)));
            *(__half2*)(Ch + (size_t)r0 * N + col)       = __halves2half2(h0, h1);
            *(__half2*)(Cl + (size_t)r0 * N + col)       = __halves2half2(l0, l1);
            *(__half2*)(Ch + (size_t)(r0 + 8) * N + col) = __halves2half2(h2, h3);
            *(__half2*)(Cl + (size_t)(r0 + 8) * N + col) = __halves2half2(l2, l3);
        }
    }
}

// ============================================================================
// Final projection GEMM: fp32 out with column mask.
// ============================================================================
__global__ __launch_bounds__(256, 2) void gemm_out(
    const float* __restrict__ bias, const float* __restrict__ cmask,
    float* __restrict__ C)
{
    extern __shared__ char sm[];
    const int tid  = threadIdx.x;
    const int warp = tid >> 5;
    const int lane = tid & 31;
    const int bx = blockIdx.x, by = blockIdx.y, bz = blockIdx.z;
    const int n0 = bx * 128, m0 = by * 128;
    const int wm = (warp >> 1) * 32;
    const int wn = (warp & 1) * 64;
    const int M = DD, N = SS, K = DKK;

    const __half* Bb = g_Bo + (size_t)bz * K * N;
    const uint32_t smb = smem_u32(sm);

    const int ar = tid >> 2, aq = tid & 3;
    const int br = tid >> 4, bq2 = tid & 15;

    auto issue = [&](int c, int st) {
        const uint32_t sb = smb + st * STAGE_SZ;
        const __half* Ahp = g_Woh + (size_t)m0 * K + c * 32;
        const __half* Bp  = Bb + (size_t)(c * 32) * N + n0;
        #pragma unroll
        for (int it = 0; it < 2; it++) {
            int r = ar + it * 64;
            cp_async16(sb + OFF_AH + (uint32_t)(r * 80 + aq * 16),
                       Ahp + (size_t)r * K + aq * 8);
            int rb = br + it * 16;
            cp_async16(sb + OFF_BH + (uint32_t)(rb * 272 + bq2 * 16),
                       Bp + (size_t)rb * N + bq2 * 8);
        }
    };

    float acc[2][8][4];
    #pragma unroll
    for (int i = 0; i < 2; i++)
        #pragma unroll
        for (int j = 0; j < 8; j++)
            #pragma unroll
            for (int t = 0; t < 4; t++) acc[i][j][t] = 0.f;

    const int nch = K >> 5;
    issue(0, 0); cp_commit();
    issue(1, 1); cp_commit();

    const int lrow16 = lane & 15;
    const int khalf  = (lane >> 4) * 8;
    const uint32_t l7 = lane & 7, mh = (lane >> 3) & 1, kh = (lane >> 4) & 1;

    for (int c = 0; c < nch; c++) {
        cp_wait<1>();
        __syncthreads();
        if (c + 2 < nch) issue(c + 2, (c + 2) % NSTAGE);
        cp_commit();

        const uint32_t bb = smb + (c % NSTAGE) * STAGE_SZ;
        #pragma unroll
        for (int s = 0; s < 2; s++) {
            const int ks = s * 16;
            uint32_t bh[4][4];
            const uint32_t brow = (uint32_t)((ks + mh * 8 + l7) * 272);
            #pragma unroll
            for (int nj = 0; nj < 4; nj++)
                ldsm_x4_t(bh[nj], bb + OFF_BH + brow +
                          (uint32_t)((wn + nj * 16 + kh * 8) * 2));
            #pragma unroll
            for (int mi = 0; mi < 2; mi++) {
                uint32_t ah[4];
                const uint32_t aoff =
                    (uint32_t)((wm + mi * 16 + lrow16) * 80 + (ks + khalf) * 2);
                ldsm_x4(ah, bb + OFF_AH + aoff);
                #pragma unroll
                for (int nj = 0; nj < 4; nj++) {
                    mma16816(acc[mi][nj * 2],     ah, bh[nj]);
                    mma16816(acc[mi][nj * 2 + 1], ah, bh[nj] + 2);
                }
            }
        }
    }

    const int r_in = lane >> 2;
    const int c_in = (lane & 3) * 2;
    float* Cb = C + (size_t)bz * M * N;
    #pragma unroll
    for (int mi = 0; mi < 2; mi++) {
        const int r0 = m0 + wm + mi * 16 + r_in;
        const float b0 = bias[r0];
        const float b1 = bias[r0 + 8];
        #pragma unroll
        for (int ni = 0; ni < 8; ni++) {
            const int col = n0 + wn + ni * 8 + c_in;
            float m0f = cmask[(size_t)bz * N + col];
            float m1f = cmask[(size_t)bz * N + col + 1];
            *(float2*)(Cb + (size_t)r0 * N + col) =
                make_float2((acc[mi][ni][0] + b0) * m0f, (acc[mi][ni][1] + b0) * m1f);
            *(float2*)(Cb + (size_t)(r0 + 8) * N + col) =
                make_float2((acc[mi][ni][2] + b1) * m0f, (acc[mi][ni][3] + b1) * m1f);
        }
    }
}

// ============================================================================
// Tensor-core windowed attention, register-resident P:
// QK^T (3-pass) -> warp-local softmax (sums stay in regs) ->
// P packed hi/lo in registers as A-operand -> O^T = P @ V^T (3-pass,
// V via non-trans ldsm on existing [d][j] layout) -> /sum, GELU, fp16 store.
// ============================================================================
#define AT_QH  0
#define AT_QL  17408
#define AT_KH  34816
#define AT_KL  52224
#define AT_VH  69632
#define AT_VL  87040
#define AT_MSK 104448   // float[128]
#define AT_SMEM 104960

__global__ __launch_bounds__(256, 2) void attn_mma(const float* __restrict__ masks)
{
    extern __shared__ char sm[];
    const uint32_t smb = smem_u32(sm);
    const int tid = threadIdx.x, warp = tid >> 5, lane = tid & 31;
    const int wh = blockIdx.x, w = wh >> 3, h = wh & 7, b = blockIdx.y;
    const size_t base = ((size_t)b * DKK + h * 64) * SS + (size_t)w * WW;

    {
        const __half* srcs[6] = { g_Qh + base, g_Ql + base, g_Kh + base,
                                  g_Kl + base, g_Vh + base, g_Vl + base };
        #pragma unroll
        for (int t = 0; t < 6; t++) {
            const uint32_t dstb = smb + t * 17408;
            #pragma unroll
            for (int it = 0; it < 4; it++) {
                int idx = tid + it * 256;
                int row = idx >> 4, ch = idx & 15;
                cp_async16(dstb + row * 272 + ch * 16,
                           srcs[t] + (size_t)row * SS + ch * 8);
            }
        }
        cp_commit();
    }
    if (tid < 32) {
        float4 mv = *(const float4*)(masks + (size_t)b * SS + w * WW + tid * 4);
        *(float4*)(sm + AT_MSK + tid * 16) = mv;
    }
    cp_wait<0>();
    __syncthreads();

    const int r_in = lane >> 2, c_in = (lane & 3) * 2;
    const uint32_t l7 = lane & 7, mh = (lane >> 3) & 1, kh = (lane >> 4) & 1;
    const int i0w = warp * 16;

    // ---- QK^T ----
    float acc[16][4];
    #pragma unroll
    for (int f = 0; f < 16; f++)
        #pragma unroll
        for (int t = 0; t < 4; t++) acc[f][t] = 0.f;

    #pragma unroll
    for (int s = 0; s < 4; s++) {
        uint32_t ah[4], al[4];
        const uint32_t aaddr = smb + (s * 16 + kh * 8 + l7) * 272 + (i0w + mh * 8) * 2;
        ldsm_x4_t(ah, aaddr + AT_QH);
        ldsm_x4_t(al, aaddr + AT_QL);
        #pragma unroll
        for (int q = 0; q < 8; q++) {
            const uint32_t baddr = smb + AT_KH +
                (s * 16 + mh * 8 + l7) * 272 + (q * 16 + kh * 8) * 2;
            uint32_t bh4[4], bl4[4];
            ldsm_x4_t(bh4, baddr);
            ldsm_x4_t(bl4, baddr + (AT_KL - AT_KH));
            const int f0 = q * 2;
            mma16816(acc[f0],     ah, bh4);
            mma16816(acc[f0],     al, bh4);
            mma16816(acc[f0],     ah, bl4);
            mma16816(acc[f0 + 1], ah, bh4 + 2);
            mma16816(acc[f0 + 1], al, bh4 + 2);
            mma16816(acc[f0 + 1], ah, bl4 + 2);
        }
    }

    // ---- mask + scale + warp-local softmax ----
    const float* mk = (const float*)(sm + AT_MSK);
    float mx0 = -1e30f, mx1 = -1e30f;
    #pragma unroll
    for (int f = 0; f < 16; f++) {
        const int j = f * 8 + c_in;
        const float mj0 = mk[j], mj1 = mk[j + 1];
        acc[f][0] = (mj0 > 0.f) ? acc[f][0] * 0.125f : -1e9f;
        acc[f][1] = (mj1 > 0.f) ? acc[f][1] * 0.125f : -1e9f;
        acc[f][2] = (mj0 > 0.f) ? acc[f][2] * 0.125f : -1e9f;
        acc[f][3] = (mj1 > 0.f) ? acc[f][3] * 0.125f : -1e9f;
        mx0 = fmaxf(mx0, fmaxf(acc[f][0], acc[f][1]));
        mx1 = fmaxf(mx1, fmaxf(acc[f][2], acc[f][3]));
    }
    mx0 = fmaxf(mx0, __shfl_xor_sync(0xffffffffu, mx0, 1));
    mx0 = fmaxf(mx0, __shfl_xor_sync(0xffffffffu, mx0, 2));
    mx1 = fmaxf(mx1, __shfl_xor_sync(0xffffffffu, mx1, 1));
    mx1 = fmaxf(mx1, __shfl_xor_sync(0xffffffffu, mx1, 2));

    float s0 = 0.f, s1 = 0.f;
    #pragma unroll
    for (int f = 0; f < 16; f++) {
        acc[f][0] = __expf(acc[f][0] - mx0);
        acc[f][1] = __expf(acc[f][1] - mx0);
        acc[f][2] = __expf(acc[f][2] - mx1);
        acc[f][3] = __expf(acc[f][3] - mx1);
        s0 += acc[f][0] + acc[f][1];
        s1 += acc[f][2] + acc[f][3];
    }
    s0 += __shfl_xor_sync(0xffffffffu, s0, 1);
    s0 += __shfl_xor_sync(0xffffffffu, s0, 2);
    s1 += __shfl_xor_sync(0xffffffffu, s1, 1);
    s1 += __shfl_xor_sync(0xffffffffu, s1, 2);

    // ---- pack P hi/lo into A-operand registers (C-frag == A-frag layout) ----
    uint32_t pAh[8][4], pAl[8][4];
    #pragma unroll
    for (int s = 0; s < 8; s++) {
        #pragma unroll
        for (int hf = 0; hf < 2; hf++) {
            const int f = 2 * s + hf;
            #pragma unroll
            for (int pr = 0; pr < 2; pr++) {
                const float x0 = acc[f][2 * pr], x1 = acc[f][2 * pr + 1];
                const __half h0 = __float2half_rn(x0), h1 = __float2half_rn(x1);
                const float r0f = __fsub_rn(x0, __half2float(h0));
                const float r1f = __fsub_rn(x1, __half2float(h1));
                __half2 hp = __halves2half2(h0, h1);
                __half2 lp = __halves2half2(__float2half_rn(r0f), __float2half_rn(r1f));
                pAh[s][hf * 2 + pr] = *(uint32_t*)&hp;
                pAl[s][hf * 2 + pr] = *(uint32_t*)&lp;
            }
        }
    }

    // ---- O^T[i][d] = P @ V^T; V [d][j] smem == col-major [k=j][n=d] ----
    float oc[8][4];
    #pragma unroll
    for (int t = 0; t < 8; t++)
        #pragma unroll
        for (int q = 0; q < 4; q++) oc[t][q] = 0.f;

    #pragma unroll
    for (int s = 0; s < 8; s++) {            // k = j, 16 per step
        #pragma unroll
        for (int dg = 0; dg < 4; dg++) {     // n = d, 16 per group
            uint32_t vh[4], vl[4];
            const uint32_t vaddr = smb + AT_VH +
                (uint32_t)((dg * 16 + l7 + kh * 8) * 272 + (s * 16 + mh * 8) * 2);
            ldsm_x4(vh, vaddr);
            ldsm_x4(vl, vaddr + (AT_VL - AT_VH));
            mma16816(oc[dg * 2],     pAh[s], vh);
            mma16816(oc[dg * 2],     pAl[s], vh);
            mma16816(oc[dg * 2],     pAh[s], vl);
            mma16816(oc[dg * 2 + 1], pAh[s], vh + 2);
            mma16816(oc[dg * 2 + 1], pAl[s], vh + 2);
            mma16816(oc[dg * 2 + 1], pAh[s], vl + 2);
        }
    }

    // ---- epilogue: /sum (register-local), exact GELU, fp16 store ----
    const float inv0 = 1.f / s0, inv1 = 1.f / s1;
    const int i0 = i0w + r_in;
    #pragma unroll
    for (int t = 0; t < 8; t++) {
        const int d = t * 8 + c_in;
        g_Bo[base + (size_t)d * SS + i0] =
            __float2half_rn(gelu_exact(oc[t][0] * inv0));
        g_Bo[base + (size_t)(d + 1) * SS + i0] =
            __float2half_rn(gelu_exact(oc[t][1] * inv0));
        g_Bo[base + (size_t)d * SS + i0 + 8] =
            __float2half_rn(gelu_exact(oc[t][2] * inv1));
        g_Bo[base + (size_t)(d + 1) * SS + i0 + 8] =
            __float2half_rn(gelu_exact(oc[t][3] * inv1));
    }
}

// ---------------------------------------------------------------------------
extern "C" void kernel_launch(void* const* d_in, const int* in_sizes, int n_in,
                              void* d_out, int out_size)
{
    const float* qk    = (const float*)d_in[0];
    const float* v     = (const float*)d_in[1];
    const float* masks = (const float*)d_in[2];
    const float* Wq    = (const float*)d_in[3];
    const float* bq    = (const float*)d_in[4];
    const float* Wk    = (const float*)d_in[5];
    const float* bk    = (const float*)d_in[6];
    const float* Wv    = (const float*)d_in[7];
    const float* bv    = (const float*)d_in[8];
    const float* Wo    = (const float*)d_in[9];
    const float* bo    = (const float*)d_in[10];
    float* out = (float*)d_out;

    __half *Bqk, *Bv, *Wqh, *Wkh, *Wvh, *Woh;
    cudaGetSymbolAddress((void**)&Bqk, g_Bqk);
    cudaGetSymbolAddress((void**)&Bv,  g_Bv);
    cudaGetSymbolAddress((void**)&Wqh, g_Wqh);
    cudaGetSymbolAddress((void**)&Wkh, g_Wkh);
    cudaGetSymbolAddress((void**)&Wvh, g_Wvh);
    cudaGetSymbolAddress((void**)&Woh, g_Woh);

    cudaFuncSetAttribute(gemm_qkv,
                         cudaFuncAttributeMaxDynamicSharedMemorySize, GSMEM_TOTAL);
    cudaFuncSetAttribute(gemm_out,
                         cudaFuncAttributeMaxDynamicSharedMemorySize, GSMEM_TOTAL);
    cudaFuncSetAttribute(attn_mma,
                         cudaFuncAttributeMaxDynamicSharedMemorySize, AT_SMEM);

    dim3 blk(256);

    // ---- conversions (merged: 2 launches) ----
    const int nW = DKK * DD / 4;               // 131072
    cvt_w4<<<4 * nW / 256, blk>>>((const float4*)Wq, (const float4*)Wk,
                                  (const float4*)Wv, (const float4*)Wo,
                                  (uint2*)Wqh, (uint2*)Wkh, (uint2*)Wvh, (uint2*)Woh);
    const int nX = NB * DD * SS / 4;
    cvt_x2<<<2 * nX / 256, blk>>>((const float4*)qk, (const float4*)v,
                                  (uint2*)Bqk, (uint2*)Bv, nX);

    // ---- merged Q/K/V projections (single launch, 12 y-blocks) ----
    gemm_qkv<<<dim3(32, 12, NB), blk, GSMEM_TOTAL>>>(bq, bk, bv);

    // ---- tensor-core attention + GELU (register-resident P) ----
    attn_mma<<<dim3(NWIN * NH, NB), blk, AT_SMEM>>>(masks);

    // ---- output projection + final mask ----
    gemm_out<<<dim3(32, 8, NB), blk, GSMEM_TOTAL>>>(bo, masks, out);
}